// round 6
// baseline (speedup 1.0000x reference)
#include <cuda_runtime.h>
#include <cuda_bf16.h>
#include <math.h>
#include <cstdint>

#define D_MODEL 1024
#define N_HEADS 16
#define HD      64
#define SEQ     2048
#define BATCH   2
#define M_ROWS  (BATCH * SEQ)   // 4096

// ---------------- scratch (__device__ globals; no allocs allowed) ----------
__device__ float g_q[M_ROWS * D_MODEL];
__device__ float g_k[M_ROWS * D_MODEL];
__device__ float g_v[M_ROWS * D_MODEL];
__device__ __nv_bfloat16 g_xh[M_ROWS * D_MODEL];
__device__ __nv_bfloat16 g_xl[M_ROWS * D_MODEL];
__device__ __nv_bfloat16 g_ah[M_ROWS * D_MODEL];
__device__ __nv_bfloat16 g_al[M_ROWS * D_MODEL];
__device__ __nv_bfloat16 g_qh[M_ROWS * D_MODEL];
__device__ __nv_bfloat16 g_ql[M_ROWS * D_MODEL];
__device__ __nv_bfloat16 g_kh[M_ROWS * D_MODEL];
__device__ __nv_bfloat16 g_kl[M_ROWS * D_MODEL];
__device__ __nv_bfloat16 g_vh[M_ROWS * D_MODEL];
__device__ __nv_bfloat16 g_vl[M_ROWS * D_MODEL];
__device__ __nv_bfloat16 g_wth[4 * D_MODEL * D_MODEL];  // W^T splits, [w][n][k]
__device__ __nv_bfloat16 g_wtl[4 * D_MODEL * D_MODEL];

// ---------------- PTX helpers (portable: sm_80+ features only) -------------
__device__ __forceinline__ uint32_t smem_to_u32(const void* p) {
    uint32_t a;
    asm("{ .reg .u64 t; cvta.to.shared.u64 t, %1; cvt.u32.u64 %0, t; }" : "=r"(a) : "l"(p));
    return a;
}
__device__ __forceinline__ void cpa16(uint32_t d, const void* s) {
    asm volatile("cp.async.cg.shared.global [%0], [%1], 16;" :: "r"(d), "l"(s));
}
#define CP_COMMIT() asm volatile("cp.async.commit_group;" ::: "memory")
#define LDSM_X4(r, a) \
    asm volatile("ldmatrix.sync.aligned.m8n8.x4.shared.b16 {%0,%1,%2,%3}, [%4];" \
                 : "=r"((r)[0]), "=r"((r)[1]), "=r"((r)[2]), "=r"((r)[3]) : "r"(a))
#define LDSM_X4_T(r, a) \
    asm volatile("ldmatrix.sync.aligned.m8n8.x4.trans.shared.b16 {%0,%1,%2,%3}, [%4];" \
                 : "=r"((r)[0]), "=r"((r)[1]), "=r"((r)[2]), "=r"((r)[3]) : "r"(a))
#define LDSM_X2(r, a) \
    asm volatile("ldmatrix.sync.aligned.m8n8.x2.shared.b16 {%0,%1}, [%2];" \
                 : "=r"((r)[0]), "=r"((r)[1]) : "r"(a))
__device__ __forceinline__ void mma_bf16(float* c, const uint32_t* a, const uint32_t* b) {
    asm volatile("mma.sync.aligned.m16n8k16.row.col.f32.bf16.bf16.f32 "
                 "{%0,%1,%2,%3}, {%4,%5,%6,%7}, {%8,%9}, {%0,%1,%2,%3};"
                 : "+f"(c[0]), "+f"(c[1]), "+f"(c[2]), "+f"(c[3])
                 : "r"(a[0]), "r"(a[1]), "r"(a[2]), "r"(a[3]), "r"(b[0]), "r"(b[1]));
}
__device__ __forceinline__ uint32_t pack_bf16x2(float lo, float hi) {
    uint32_t r;
    asm("cvt.rn.bf16x2.f32 %0, %1, %2;" : "=r"(r) : "f"(hi), "f"(lo));
    return r;
}
__device__ __forceinline__ float bf_lo(uint32_t u) { return __uint_as_float(u << 16); }
__device__ __forceinline__ float bf_hi(uint32_t u) { return __uint_as_float(u & 0xffff0000u); }

// GEMM tiles: 64B logical rows (4 chunks); 128B line = 2 rows.
__device__ __forceinline__ uint32_t swz(int r, int ch) {
    return (uint32_t)(((r >> 1) << 7) + (((((r & 1) << 2) + ch) ^ ((r >> 1) & 7)) << 4));
}
// Attention tiles: 128B rows (8 chunks), SW128 atom. ch in 0..7.
__device__ __forceinline__ uint32_t swzA(int r, int ch) {
    return (uint32_t)((r << 7) + ((ch ^ (r & 7)) << 4));
}

// fast exp on FMA/ALU pipes (no MUFU): valid for x <= 0, rel err ~2.4e-6
__device__ __forceinline__ float fexp(float x) {
    x = fmaxf(x, -80.0f);
    const float t = x * 1.4426950408889634f;
    const float z = t + 12582912.0f;              // round-to-nearest int
    const int   n = __float_as_int(z) - 0x4B400000;
    const float f = t - (z - 12582912.0f);        // in [-0.5, 0.5]
    float p = 0.0013333558f;
    p = fmaf(p, f, 0.009618129f);
    p = fmaf(p, f, 0.05550411f);
    p = fmaf(p, f, 0.24022651f);
    p = fmaf(p, f, 0.69314718f);
    p = fmaf(p, f, 1.0f);
    return p * __int_as_float((n + 127) << 23);
}

// ---------------------------------------------------------------------------
// split: fp32 -> (hi, lo) bf16, elementwise
// ---------------------------------------------------------------------------
__global__ __launch_bounds__(256) void split_kernel(const float* __restrict__ src,
                                                    __nv_bfloat16* __restrict__ hi,
                                                    __nv_bfloat16* __restrict__ lo) {
    const int i = (blockIdx.x * 256 + threadIdx.x) * 4;
    float4 v = *(const float4*)(src + i);
    __nv_bfloat16 h0 = __float2bfloat16_rn(v.x), h1 = __float2bfloat16_rn(v.y);
    __nv_bfloat16 h2 = __float2bfloat16_rn(v.z), h3 = __float2bfloat16_rn(v.w);
    __nv_bfloat162* H = (__nv_bfloat162*)(hi + i);
    __nv_bfloat162* L = (__nv_bfloat162*)(lo + i);
    H[0] = __nv_bfloat162(h0, h1);
    H[1] = __nv_bfloat162(h2, h3);
    L[0] = __nv_bfloat162(__float2bfloat16_rn(v.x - __bfloat162float(h0)),
                          __float2bfloat16_rn(v.y - __bfloat162float(h1)));
    L[1] = __nv_bfloat162(__float2bfloat16_rn(v.z - __bfloat162float(h2)),
                          __float2bfloat16_rn(v.w - __bfloat162float(h3)));
}

// ---------------------------------------------------------------------------
// weight transpose + split
// ---------------------------------------------------------------------------
__global__ __launch_bounds__(256) void wsplit_kernel(const float* __restrict__ w0,
                                                     const float* __restrict__ w1,
                                                     const float* __restrict__ w2,
                                                     const float* __restrict__ w3) {
    __shared__ float t[32][33];
    const float* W = (blockIdx.z == 0) ? w0 : (blockIdx.z == 1) ? w1 : (blockIdx.z == 2) ? w2 : w3;
    const int nb = blockIdx.x * 32, kb = blockIdx.y * 32;
    const int tx = threadIdx.x & 31, ty = threadIdx.x >> 5;
#pragma unroll
    for (int i = 0; i < 32; i += 8)
        t[ty + i][tx] = W[(size_t)(kb + ty + i) * D_MODEL + nb + tx];
    __syncthreads();
    const size_t base = (size_t)blockIdx.z * D_MODEL * D_MODEL;
#pragma unroll
    for (int i = 0; i < 32; i += 8) {
        float v = t[tx][ty + i];
        __nv_bfloat16 h = __float2bfloat16_rn(v);
        size_t o = base + (size_t)(nb + ty + i) * D_MODEL + kb + tx;
        g_wth[o] = h;
        g_wtl[o] = __float2bfloat16_rn(v - __bfloat162float(h));
    }
}

// ---------------------------------------------------------------------------
// HMMA split-bf16 GEMM, swizzled smem, 2 CTAs/SM.
// C[M, N] = A[M,1024] @ B^T; B stored [N][1024]; N-tile picks output buffer
// (QKV fused: N=3072, C = {C0,C1,C2}[n>>10]).
// ---------------------------------------------------------------------------
#define GMAT 8192                     // bytes per matrix tile (128 rows x 64B)
#define GSTAGE (4 * GMAT)             // Ah, Al, Bh, Bl
#define GEMM_SMEM (2 * GSTAGE)        // 65536 bytes

__global__ __launch_bounds__(256, 2) void hmma_gemm(const __nv_bfloat16* __restrict__ Ah,
                                                    const __nv_bfloat16* __restrict__ Al,
                                                    const __nv_bfloat16* __restrict__ Bh,
                                                    const __nv_bfloat16* __restrict__ Bl,
                                                    float* __restrict__ C0,
                                                    float* __restrict__ C1,
                                                    float* __restrict__ C2) {
    extern __shared__ char smg[];
    const uint32_t u0 = smem_to_u32(smg);

    const int tid = threadIdx.x, warp = tid >> 5, lane = tid & 31;
    const int tm = blockIdx.y * 128;
    const int tnG = blockIdx.x * 128;           // global n (may exceed 1024)
    const int tn = tnG & 1023;
    float* C = ((tnG >> 10) == 0) ? C0 : ((tnG >> 10) == 1) ? C1 : C2;
    const int wm = (warp >> 2) * 64, wn = (warp & 3) * 32;

    const int c0 = tid * 2, c1 = tid * 2 + 1;
    const int r0c = c0 >> 2, h0c = c0 & 3;
    const int r1c = c1 >> 2, h1c = c1 & 3;

    auto load_stage = [&](int s, int kc) {
        const uint32_t ub = u0 + s * GSTAGE;
        {
            const uint32_t sw = swz(r0c, h0c);
            const size_t ga = (size_t)(tm + r0c) * D_MODEL + kc + h0c * 8;
            const size_t gb = (size_t)(tnG + r0c) * D_MODEL + kc + h0c * 8;
            cpa16(ub + sw,            Ah + ga);
            cpa16(ub + GMAT + sw,     Al + ga);
            cpa16(ub + 2 * GMAT + sw, Bh + gb);
            cpa16(ub + 3 * GMAT + sw, Bl + gb);
        }
        {
            const uint32_t sw = swz(r1c, h1c);
            const size_t ga = (size_t)(tm + r1c) * D_MODEL + kc + h1c * 8;
            const size_t gb = (size_t)(tnG + r1c) * D_MODEL + kc + h1c * 8;
            cpa16(ub + sw,            Ah + ga);
            cpa16(ub + GMAT + sw,     Al + ga);
            cpa16(ub + 2 * GMAT + sw, Bh + gb);
            cpa16(ub + 3 * GMAT + sw, Bl + gb);
        }
        CP_COMMIT();
    };

    float acc[4][4][4] = {};

    load_stage(0, 0);
    const int NKB = D_MODEL / 32;
    for (int kb = 0; kb < NKB; ++kb) {
        const int s = kb & 1;
        if (kb + 1 < NKB) {
            load_stage(s ^ 1, (kb + 1) * 32);
            asm volatile("cp.async.wait_group 1;" ::: "memory");
        } else {
            asm volatile("cp.async.wait_group 0;" ::: "memory");
        }
        __syncthreads();
        const uint32_t uAh = u0 + s * GSTAGE;
        const uint32_t uAl = uAh + GMAT;
        const uint32_t uBh = uAh + 2 * GMAT;
        const uint32_t uBl = uAh + 3 * GMAT;

#pragma unroll
        for (int kk = 0; kk < 2; ++kk) {
            uint32_t bh[4][2], bl[4][2];
            const int brow = wn + (lane & 7);
            const int bch = kk * 2 + ((lane >> 3) & 1);
#pragma unroll
            for (int nt = 0; nt < 4; ++nt) {
                const uint32_t off = swz(brow + nt * 8, bch);
                LDSM_X2(bh[nt], uBh + off);
                LDSM_X2(bl[nt], uBl + off);
            }
            const int arow = wm + (lane & 15);
            const int ach = kk * 2 + (lane >> 4);
#pragma unroll
            for (int mt = 0; mt < 4; ++mt) {
                const uint32_t off = swz(arow + mt * 16, ach);
                uint32_t ah[4], al[4];
                LDSM_X4(ah, uAh + off);
                LDSM_X4(al, uAl + off);
#pragma unroll
                for (int nt = 0; nt < 4; ++nt) {
                    mma_bf16(acc[mt][nt], ah, bh[nt]);
                    mma_bf16(acc[mt][nt], ah, bl[nt]);
                    mma_bf16(acc[mt][nt], al, bh[nt]);
                }
            }
        }
        __syncthreads();
    }

#pragma unroll
    for (int mt = 0; mt < 4; ++mt) {
#pragma unroll
        for (int nt = 0; nt < 4; ++nt) {
            const int r0 = tm + wm + mt * 16 + (lane >> 2);
            const int cc = tn + wn + nt * 8 + 2 * (lane & 3);
            *(float2*)&C[(size_t)r0 * D_MODEL + cc] = make_float2(acc[mt][nt][0], acc[mt][nt][1]);
            *(float2*)&C[(size_t)(r0 + 8) * D_MODEL + cc] = make_float2(acc[mt][nt][2], acc[mt][nt][3]);
        }
    }
}

// ---------------------------------------------------------------------------
// Fused per-head RMSNorm + RoPE -> split bf16 outputs
// ---------------------------------------------------------------------------
__global__ __launch_bounds__(256) void rmsrope_kernel(const float* __restrict__ w_q,
                                                      const float* __restrict__ w_k) {
    const int gw   = (blockIdx.x * blockDim.x + threadIdx.x) >> 5;
    const int lane = threadIdx.x & 31;
    const float* src = (blockIdx.y == 0) ? g_q : g_k;
    const float* w   = (blockIdx.y == 0) ? w_q : w_k;
    __nv_bfloat16* oh = (blockIdx.y == 0) ? g_qh : g_kh;
    __nv_bfloat16* ol = (blockIdx.y == 0) ? g_ql : g_kl;
    const int t = (gw / N_HEADS) % SEQ;
    const size_t base = (size_t)gw * HD;

    float x1 = src[base + lane];
    float x2 = src[base + lane + 32];
    float ss = x1 * x1 + x2 * x2;
#pragma unroll
    for (int o = 16; o; o >>= 1) ss += __shfl_xor_sync(0xffffffffu, ss, o);
    const float r = rsqrtf(ss * (1.0f / 64.0f) + 1e-6f);
    x1 *= r * w[lane];
    x2 *= r * w[lane + 32];
    const float inv = exp2f(-(float)lane * 0.41524101186091903f);
    const float ang = (float)t * inv;
    float sn, cs;
    sincosf(ang, &sn, &cs);
    const float y1 = x1 * cs - x2 * sn;
    const float y2 = x2 * cs + x1 * sn;

    __nv_bfloat16 h1 = __float2bfloat16_rn(y1);
    __nv_bfloat16 h2 = __float2bfloat16_rn(y2);
    oh[base + lane]      = h1;
    oh[base + lane + 32] = h2;
    ol[base + lane]      = __float2bfloat16_rn(y1 - __bfloat162float(h1));
    ol[base + lane + 32] = __float2bfloat16_rn(y2 - __bfloat162float(h2));
}

// ---------------------------------------------------------------------------
// HMMA flash attention, split-bf16, SW128 smem, poly-exp softmax.
// CTA = 128 q-rows x head x batch, 8 warps, K-block 64, double-buffered K/V.
// Rows are 128B (HD=64 bf16) -> swzA with ch 0..7.
// ---------------------------------------------------------------------------
#define AQMAT 16384                   // q matrix tile: 128 rows x 128B
#define AKMAT 8192                    // kv matrix tile: 64 rows x 128B
#define AKSTG (4 * AKMAT)             // Kh, Kl, Vh, Vl per stage
#define ATT_SMEM (2 * AQMAT + 2 * AKSTG)   // 98304 bytes

__global__ __launch_bounds__(256) void attn_hmma() {
    extern __shared__ char smA[];
    const uint32_t u0  = smem_to_u32(smA);
    const uint32_t uQh = u0;
    const uint32_t uQl = u0 + AQMAT;

    const int tid = threadIdx.x, warp = tid >> 5, lane = tid & 31;
    const int qt = (int)(gridDim.x - 1) - (int)blockIdx.x;   // long CTAs first
    const int h = blockIdx.y, b = blockIdx.z;
    const int wm = warp * 16;
    const size_t gq0 = ((size_t)b * SEQ + (size_t)qt * 128) * D_MODEL + h * HD;

    // ---- load q tile: 128 rows x 8 chunks = 1024 chunks, 4 per thread
#pragma unroll
    for (int c = 0; c < 4; ++c) {
        const int idx = tid + c * 256;
        const int r = idx >> 3, ch = idx & 7;
        const uint32_t sw = swzA(r, ch);
        const size_t ga = gq0 + (size_t)r * D_MODEL + ch * 8;
        cpa16(uQh + sw, g_qh + ga);
        cpa16(uQl + sw, g_ql + ga);
    }
    CP_COMMIT();

    auto load_kv = [&](int s, int kb) {
        const uint32_t ub = u0 + 2 * AQMAT + s * AKSTG;
#pragma unroll
        for (int c = 0; c < 2; ++c) {
            const int idx = tid * 2 + c;             // 512 chunks = 64 rows x 8
            const int r = idx >> 3, ch = idx & 7;
            const uint32_t sw = swzA(r, ch);
            const size_t ga = ((size_t)b * SEQ + (size_t)kb * 64 + r) * D_MODEL + h * HD + ch * 8;
            cpa16(ub + sw,             g_kh + ga);
            cpa16(ub + AKMAT + sw,     g_kl + ga);
            cpa16(ub + 2 * AKMAT + sw, g_vh + ga);
            cpa16(ub + 3 * AKMAT + sw, g_vl + ga);
        }
        CP_COMMIT();
    };

    load_kv(0, 0);
    asm volatile("cp.async.wait_group 0;" ::: "memory");
    __syncthreads();

    // ---- q fragments (A, m16k16), once
    uint32_t qfh[4][4], qfl[4][4];
    {
        const int arow = wm + (lane & 15);
#pragma unroll
        for (int ks = 0; ks < 4; ++ks) {
            const uint32_t off = swzA(arow, ks * 2 + (lane >> 4));
            LDSM_X4(qfh[ks], uQh + off);
            LDSM_X4(qfl[ks], uQl + off);
        }
    }

    float acc[8][4] = {};
    float m0 = -1e30f, m1 = -1e30f, l0 = 0.f, l1 = 0.f;
    const int nkb = 2 * qt + 2;
    const int qrow0 = qt * 128 + wm;

    for (int kb = 0; kb < nkb; ++kb) {
        const int s = kb & 1;
        if (kb + 1 < nkb) {
            load_kv(s ^ 1, kb + 1);
            asm volatile("cp.async.wait_group 1;" ::: "memory");
        } else {
            asm volatile("cp.async.wait_group 0;" ::: "memory");
        }
        __syncthreads();

        const bool active = (kb * 64 <= qrow0 + 15);
        if (active) {
            const uint32_t uKh = u0 + 2 * AQMAT + s * AKSTG;
            const uint32_t uKl = uKh + AKMAT;
            const uint32_t uVh = uKh + 2 * AKMAT;
            const uint32_t uVl = uKh + 3 * AKMAT;

            // ---- S = q k^T (3-term split)
            float sc[8][4] = {};
#pragma unroll
            for (int ks = 0; ks < 4; ++ks) {
                const int bch = ks * 2 + ((lane >> 3) & 1);
                const int brow = (lane & 7) + ((lane >> 4) << 3);
#pragma unroll
                for (int np = 0; np < 4; ++np) {
                    const uint32_t boff = swzA(np * 16 + brow, bch);
                    uint32_t bh[4], bl[4];
                    LDSM_X4(bh, uKh + boff);
                    LDSM_X4(bl, uKl + boff);
                    mma_bf16(sc[2 * np],     qfh[ks], &bh[0]);
                    mma_bf16(sc[2 * np],     qfh[ks], &bl[0]);
                    mma_bf16(sc[2 * np],     qfl[ks], &bh[0]);
                    mma_bf16(sc[2 * np + 1], qfh[ks], &bh[2]);
                    mma_bf16(sc[2 * np + 1], qfh[ks], &bl[2]);
                    mma_bf16(sc[2 * np + 1], qfl[ks], &bh[2]);
                }
            }

            // ---- scale + mask + online softmax (poly exp, no MUFU)
            const float SCL = 0.125f;
            const bool domask = (kb * 64 + 63 > qrow0);
            const int r0 = qrow0 + (lane >> 2);
            float mt0 = -1e30f, mt1 = -1e30f;
#pragma unroll
            for (int nt = 0; nt < 8; ++nt) {
#pragma unroll
                for (int j = 0; j < 4; ++j) sc[nt][j] *= SCL;
                if (domask) {
                    const int colb = kb * 64 + nt * 8 + 2 * (lane & 3);
                    if (colb     > r0)     sc[nt][0] = -1e30f;
                    if (colb + 1 > r0)     sc[nt][1] = -1e30f;
                    if (colb     > r0 + 8) sc[nt][2] = -1e30f;
                    if (colb + 1 > r0 + 8) sc[nt][3] = -1e30f;
                }
                mt0 = fmaxf(mt0, fmaxf(sc[nt][0], sc[nt][1]));
                mt1 = fmaxf(mt1, fmaxf(sc[nt][2], sc[nt][3]));
            }
            mt0 = fmaxf(mt0, __shfl_xor_sync(0xffffffffu, mt0, 1));
            mt0 = fmaxf(mt0, __shfl_xor_sync(0xffffffffu, mt0, 2));
            mt1 = fmaxf(mt1, __shfl_xor_sync(0xffffffffu, mt1, 1));
            mt1 = fmaxf(mt1, __shfl_xor_sync(0xffffffffu, mt1, 2));
            const float mn0 = fmaxf(m0, mt0), mn1 = fmaxf(m1, mt1);
            const float a0 = fexp(m0 - mn0), a1 = fexp(m1 - mn1);
            m0 = mn0; m1 = mn1;

            float s0 = 0.f, s1 = 0.f;
            uint32_t ph[4][4], pl[4][4];
#pragma unroll
            for (int nt = 0; nt < 8; ++nt) {
                const float p0 = fexp(sc[nt][0] - mn0);
                const float p1 = fexp(sc[nt][1] - mn0);
                const float p2 = fexp(sc[nt][2] - mn1);
                const float p3 = fexp(sc[nt][3] - mn1);
                s0 += p0 + p1;
                s1 += p2 + p3;
                const uint32_t hA = pack_bf16x2(p0, p1);
                const uint32_t hB = pack_bf16x2(p2, p3);
                const uint32_t lA = pack_bf16x2(p0 - bf_lo(hA), p1 - bf_hi(hA));
                const uint32_t lB = pack_bf16x2(p2 - bf_lo(hB), p3 - bf_hi(hB));
                const int ks = nt >> 1, pos = (nt & 1) * 2;
                ph[ks][pos] = hA; ph[ks][pos + 1] = hB;
                pl[ks][pos] = lA; pl[ks][pos + 1] = lB;
            }
            s0 += __shfl_xor_sync(0xffffffffu, s0, 1);
            s0 += __shfl_xor_sync(0xffffffffu, s0, 2);
            s1 += __shfl_xor_sync(0xffffffffu, s1, 1);
            s1 += __shfl_xor_sync(0xffffffffu, s1, 2);
            l0 = l0 * a0 + s0;
            l1 = l1 * a1 + s1;
#pragma unroll
            for (int nt = 0; nt < 8; ++nt) {
                acc[nt][0] *= a0; acc[nt][1] *= a0;
                acc[nt][2] *= a1; acc[nt][3] *= a1;
            }

            // ---- O += P V (3-term split, V via ldmatrix.trans)
#pragma unroll
            for (int ks = 0; ks < 4; ++ks) {
                const int vrow = ks * 16 + (lane & 7) + (((lane >> 3) & 1) << 3);
#pragma unroll
                for (int np = 0; np < 4; ++np) {
                    const uint32_t voff = swzA(vrow, np * 2 + (lane >> 4));
                    uint32_t vh4[4], vl4[4];
                    LDSM_X4_T(vh4, uVh + voff);
                    LDSM_X4_T(vl4, uVl + voff);
                    mma_bf16(acc[2 * np],     ph[ks], &vh4[0]);
                    mma_bf16(acc[2 * np],     ph[ks], &vl4[0]);
                    mma_bf16(acc[2 * np],     pl[ks], &vh4[0]);
                    mma_bf16(acc[2 * np + 1], ph[ks], &vh4[2]);
                    mma_bf16(acc[2 * np + 1], ph[ks], &vl4[2]);
                    mma_bf16(acc[2 * np + 1], pl[ks], &vh4[2]);
                }
            }
        }
        __syncthreads();
    }

    // ---- epilogue: normalize, split to bf16 hi/lo, write O-proj A buffers
    const float i0 = 1.0f / l0, i1 = 1.0f / l1;
    const size_t gr0 = ((size_t)b * SEQ + qrow0 + (lane >> 2)) * D_MODEL + h * HD + 2 * (lane & 3);
#pragma unroll
    for (int nt = 0; nt < 8; ++nt) {
        const float o0 = acc[nt][0] * i0, o1 = acc[nt][1] * i0;
        const float o2 = acc[nt][2] * i1, o3 = acc[nt][3] * i1;
        const uint32_t hA = pack_bf16x2(o0, o1);
        const uint32_t hB = pack_bf16x2(o2, o3);
        const uint32_t lA = pack_bf16x2(o0 - bf_lo(hA), o1 - bf_hi(hA));
        const uint32_t lB = pack_bf16x2(o2 - bf_lo(hB), o3 - bf_hi(hB));
        *(uint32_t*)&g_ah[gr0 + nt * 8]               = hA;
        *(uint32_t*)&g_al[gr0 + nt * 8]               = lA;
        *(uint32_t*)&g_ah[gr0 + 8 * D_MODEL + nt * 8] = hB;
        *(uint32_t*)&g_al[gr0 + 8 * D_MODEL + nt * 8] = lB;
    }
}

// ---------------------------------------------------------------------------
extern "C" void kernel_launch(void* const* d_in, const int* in_sizes, int n_in,
                              void* d_out, int out_size) {
    const float* x  = (const float*)d_in[0];
    const float* Wq = (const float*)d_in[1];
    const float* Wk = (const float*)d_in[2];
    const float* Wv = (const float*)d_in[3];
    const float* Wo = (const float*)d_in[4];
    const float* qw = (const float*)d_in[5];
    const float* kw = (const float*)d_in[6];
    float* out = (float*)d_out;

    float *qb, *kb, *vb;
    __nv_bfloat16 *xh, *xl, *ah, *al, *vh, *vl, *wth, *wtl;
    cudaGetSymbolAddress((void**)&qb, g_q);
    cudaGetSymbolAddress((void**)&kb, g_k);
    cudaGetSymbolAddress((void**)&vb, g_v);
    cudaGetSymbolAddress((void**)&xh, g_xh);
    cudaGetSymbolAddress((void**)&xl, g_xl);
    cudaGetSymbolAddress((void**)&ah, g_ah);
    cudaGetSymbolAddress((void**)&al, g_al);
    cudaGetSymbolAddress((void**)&vh, g_vh);
    cudaGetSymbolAddress((void**)&vl, g_vl);
    cudaGetSymbolAddress((void**)&wth, g_wth);
    cudaGetSymbolAddress((void**)&wtl, g_wtl);

    const int NEL = M_ROWS * D_MODEL;
    const size_t WSZ = (size_t)D_MODEL * D_MODEL;

    split_kernel<<<NEL / (256 * 4), 256>>>(x, xh, xl);
    wsplit_kernel<<<dim3(32, 32, 4), 256>>>(Wq, Wk, Wv, Wo);

    cudaFuncSetAttribute(hmma_gemm, cudaFuncAttributeMaxDynamicSharedMemorySize, GEMM_SMEM);
    // fused QKV: N = 3072 (wth slots 0..2 contiguous)
    hmma_gemm<<<dim3(3 * D_MODEL / 128, M_ROWS / 128), 256, GEMM_SMEM>>>(
        xh, xl, wth, wtl, qb, kb, vb);

    rmsrope_kernel<<<dim3((M_ROWS * N_HEADS) / 8, 2), 256>>>(qw, kw);
    split_kernel<<<NEL / (256 * 4), 256>>>(vb, vh, vl);

    cudaFuncSetAttribute(attn_hmma, cudaFuncAttributeMaxDynamicSharedMemorySize, ATT_SMEM);
    attn_hmma<<<dim3(SEQ / 128, N_HEADS, BATCH), 256, ATT_SMEM>>>();

    // O projection
    hmma_gemm<<<dim3(D_MODEL / 128, M_ROWS / 128), 256, GEMM_SMEM>>>(
        ah, al, wth + 3 * WSZ, wtl + 3 * WSZ, out, out, out);
}

// round 7
// speedup vs baseline: 1.8099x; 1.8099x over previous
#include <cuda_runtime.h>
#include <cuda_bf16.h>
#include <math.h>
#include <cstdint>

#define D_MODEL 1024
#define N_HEADS 16
#define HD      64
#define SEQ     2048
#define BATCH   2
#define M_ROWS  (BATCH * SEQ)   // 4096

// ---------------- scratch (__device__ globals; no allocs allowed) ----------
__device__ float g_q[M_ROWS * D_MODEL];
__device__ float g_k[M_ROWS * D_MODEL];
__device__ __nv_bfloat16 g_xh[M_ROWS * D_MODEL];
__device__ __nv_bfloat16 g_xl[M_ROWS * D_MODEL];
__device__ __nv_bfloat16 g_ah[M_ROWS * D_MODEL];
__device__ __nv_bfloat16 g_al[M_ROWS * D_MODEL];
__device__ __nv_bfloat16 g_qh[M_ROWS * D_MODEL];
__device__ __nv_bfloat16 g_ql[M_ROWS * D_MODEL];
__device__ __nv_bfloat16 g_kh[M_ROWS * D_MODEL];
__device__ __nv_bfloat16 g_kl[M_ROWS * D_MODEL];
__device__ __nv_bfloat16 g_vh[M_ROWS * D_MODEL];
__device__ __nv_bfloat16 g_vl[M_ROWS * D_MODEL];
__device__ __nv_bfloat16 g_wth[4 * D_MODEL * D_MODEL];  // W^T splits, [w][n][k]
__device__ __nv_bfloat16 g_wtl[4 * D_MODEL * D_MODEL];

// ---------------- PTX helpers (portable: sm_80+ features only) -------------
__device__ __forceinline__ uint32_t smem_to_u32(const void* p) {
    uint32_t a;
    asm("{ .reg .u64 t; cvta.to.shared.u64 t, %1; cvt.u32.u64 %0, t; }" : "=r"(a) : "l"(p));
    return a;
}
__device__ __forceinline__ void cpa16(uint32_t d, const void* s) {
    asm volatile("cp.async.cg.shared.global [%0], [%1], 16;" :: "r"(d), "l"(s));
}
#define CP_COMMIT() asm volatile("cp.async.commit_group;" ::: "memory")
#define LDSM_X4(r, a) \
    asm volatile("ldmatrix.sync.aligned.m8n8.x4.shared.b16 {%0,%1,%2,%3}, [%4];" \
                 : "=r"((r)[0]), "=r"((r)[1]), "=r"((r)[2]), "=r"((r)[3]) : "r"(a))
#define LDSM_X4_T(r, a) \
    asm volatile("ldmatrix.sync.aligned.m8n8.x4.trans.shared.b16 {%0,%1,%2,%3}, [%4];" \
                 : "=r"((r)[0]), "=r"((r)[1]), "=r"((r)[2]), "=r"((r)[3]) : "r"(a))
#define LDSM_X2(r, a) \
    asm volatile("ldmatrix.sync.aligned.m8n8.x2.shared.b16 {%0,%1}, [%2];" \
                 : "=r"((r)[0]), "=r"((r)[1]) : "r"(a))
__device__ __forceinline__ void mma_bf16(float* c, const uint32_t* a, const uint32_t* b) {
    asm volatile("mma.sync.aligned.m16n8k16.row.col.f32.bf16.bf16.f32 "
                 "{%0,%1,%2,%3}, {%4,%5,%6,%7}, {%8,%9}, {%0,%1,%2,%3};"
                 : "+f"(c[0]), "+f"(c[1]), "+f"(c[2]), "+f"(c[3])
                 : "r"(a[0]), "r"(a[1]), "r"(a[2]), "r"(a[3]), "r"(b[0]), "r"(b[1]));
}
__device__ __forceinline__ uint32_t pack_bf16x2(float lo, float hi) {
    uint32_t r;
    asm("cvt.rn.bf16x2.f32 %0, %1, %2;" : "=r"(r) : "f"(hi), "f"(lo));
    return r;
}
__device__ __forceinline__ float bf_lo(uint32_t u) { return __uint_as_float(u << 16); }
__device__ __forceinline__ float bf_hi(uint32_t u) { return __uint_as_float(u & 0xffff0000u); }

// GEMM tiles: 64B logical rows (4 chunks); 128B line = 2 rows.
__device__ __forceinline__ uint32_t swz(int r, int ch) {
    return (uint32_t)(((r >> 1) << 7) + (((((r & 1) << 2) + ch) ^ ((r >> 1) & 7)) << 4));
}
// Attention tiles: 128B rows (8 chunks), SW128 atom. ch in 0..7.
__device__ __forceinline__ uint32_t swzA(int r, int ch) {
    return (uint32_t)((r << 7) + ((ch ^ (r & 7)) << 4));
}

// 2^y on FMA/ALU pipes, y <= 0 (poly half of the hybrid softmax)
__device__ __forceinline__ float fexp2(float y) {
    y = fmaxf(y, -120.0f);
    const float z = y + 12582912.0f;              // round-to-nearest int
    const int   n = __float_as_int(z) - 0x4B400000;
    const float f = y - (z - 12582912.0f);        // in [-0.5, 0.5]
    float p = 0.0013333558f;
    p = fmaf(p, f, 0.009618129f);
    p = fmaf(p, f, 0.05550411f);
    p = fmaf(p, f, 0.24022651f);
    p = fmaf(p, f, 0.69314718f);
    p = fmaf(p, f, 1.0f);
    return p * __int_as_float((n + 127) << 23);
}

// ---------------------------------------------------------------------------
// split: fp32 -> (hi, lo) bf16, elementwise
// ---------------------------------------------------------------------------
__global__ __launch_bounds__(256) void split_kernel(const float* __restrict__ src,
                                                    __nv_bfloat16* __restrict__ hi,
                                                    __nv_bfloat16* __restrict__ lo) {
    const int i = (blockIdx.x * 256 + threadIdx.x) * 4;
    float4 v = *(const float4*)(src + i);
    __nv_bfloat16 h0 = __float2bfloat16_rn(v.x), h1 = __float2bfloat16_rn(v.y);
    __nv_bfloat16 h2 = __float2bfloat16_rn(v.z), h3 = __float2bfloat16_rn(v.w);
    __nv_bfloat162* H = (__nv_bfloat162*)(hi + i);
    __nv_bfloat162* L = (__nv_bfloat162*)(lo + i);
    H[0] = __nv_bfloat162(h0, h1);
    H[1] = __nv_bfloat162(h2, h3);
    L[0] = __nv_bfloat162(__float2bfloat16_rn(v.x - __bfloat162float(h0)),
                          __float2bfloat16_rn(v.y - __bfloat162float(h1)));
    L[1] = __nv_bfloat162(__float2bfloat16_rn(v.z - __bfloat162float(h2)),
                          __float2bfloat16_rn(v.w - __bfloat162float(h3)));
}

// ---------------------------------------------------------------------------
// weight transpose + split
// ---------------------------------------------------------------------------
__global__ __launch_bounds__(256) void wsplit_kernel(const float* __restrict__ w0,
                                                     const float* __restrict__ w1,
                                                     const float* __restrict__ w2,
                                                     const float* __restrict__ w3) {
    __shared__ float t[32][33];
    const float* W = (blockIdx.z == 0) ? w0 : (blockIdx.z == 1) ? w1 : (blockIdx.z == 2) ? w2 : w3;
    const int nb = blockIdx.x * 32, kb = blockIdx.y * 32;
    const int tx = threadIdx.x & 31, ty = threadIdx.x >> 5;
#pragma unroll
    for (int i = 0; i < 32; i += 8)
        t[ty + i][tx] = W[(size_t)(kb + ty + i) * D_MODEL + nb + tx];
    __syncthreads();
    const size_t base = (size_t)blockIdx.z * D_MODEL * D_MODEL;
#pragma unroll
    for (int i = 0; i < 32; i += 8) {
        float v = t[tx][ty + i];
        __nv_bfloat16 h = __float2bfloat16_rn(v);
        size_t o = base + (size_t)(nb + ty + i) * D_MODEL + kb + tx;
        g_wth[o] = h;
        g_wtl[o] = __float2bfloat16_rn(v - __bfloat162float(h));
    }
}

// ---------------------------------------------------------------------------
// HMMA split-bf16 GEMM, swizzled smem, 2 CTAs/SM.
// QKV fused: N=3072; n-tile 0/1 -> f32 C0/C1; n-tile 2 -> split bf16 Vh/Vl.
// O-proj: N=1024 -> f32 C0.
// ---------------------------------------------------------------------------
#define GMAT 8192                     // bytes per matrix tile (128 rows x 64B)
#define GSTAGE (4 * GMAT)             // Ah, Al, Bh, Bl
#define GEMM_SMEM (2 * GSTAGE)        // 65536 bytes

__global__ __launch_bounds__(256, 2) void hmma_gemm(const __nv_bfloat16* __restrict__ Ah,
                                                    const __nv_bfloat16* __restrict__ Al,
                                                    const __nv_bfloat16* __restrict__ Bh,
                                                    const __nv_bfloat16* __restrict__ Bl,
                                                    float* __restrict__ C0,
                                                    float* __restrict__ C1,
                                                    __nv_bfloat16* __restrict__ Vh,
                                                    __nv_bfloat16* __restrict__ Vl) {
    extern __shared__ char smg[];
    const uint32_t u0 = smem_to_u32(smg);

    const int tid = threadIdx.x, warp = tid >> 5, lane = tid & 31;
    const int tm = blockIdx.y * 128;
    const int tnG = blockIdx.x * 128;           // global n (may exceed 1024)
    const int tn = tnG & 1023;
    const int seg = tnG >> 10;
    const int wm = (warp >> 2) * 64, wn = (warp & 3) * 32;

    const int c0 = tid * 2, c1 = tid * 2 + 1;
    const int r0c = c0 >> 2, h0c = c0 & 3;
    const int r1c = c1 >> 2, h1c = c1 & 3;

    auto load_stage = [&](int s, int kc) {
        const uint32_t ub = u0 + s * GSTAGE;
        {
            const uint32_t sw = swz(r0c, h0c);
            const size_t ga = (size_t)(tm + r0c) * D_MODEL + kc + h0c * 8;
            const size_t gb = (size_t)(tnG + r0c) * D_MODEL + kc + h0c * 8;
            cpa16(ub + sw,            Ah + ga);
            cpa16(ub + GMAT + sw,     Al + ga);
            cpa16(ub + 2 * GMAT + sw, Bh + gb);
            cpa16(ub + 3 * GMAT + sw, Bl + gb);
        }
        {
            const uint32_t sw = swz(r1c, h1c);
            const size_t ga = (size_t)(tm + r1c) * D_MODEL + kc + h1c * 8;
            const size_t gb = (size_t)(tnG + r1c) * D_MODEL + kc + h1c * 8;
            cpa16(ub + sw,            Ah + ga);
            cpa16(ub + GMAT + sw,     Al + ga);
            cpa16(ub + 2 * GMAT + sw, Bh + gb);
            cpa16(ub + 3 * GMAT + sw, Bl + gb);
        }
        CP_COMMIT();
    };

    float acc[4][4][4] = {};

    load_stage(0, 0);
    const int NKB = D_MODEL / 32;
    for (int kb = 0; kb < NKB; ++kb) {
        const int s = kb & 1;
        if (kb + 1 < NKB) {
            load_stage(s ^ 1, (kb + 1) * 32);
            asm volatile("cp.async.wait_group 1;" ::: "memory");
        } else {
            asm volatile("cp.async.wait_group 0;" ::: "memory");
        }
        __syncthreads();
        const uint32_t uAh = u0 + s * GSTAGE;
        const uint32_t uAl = uAh + GMAT;
        const uint32_t uBh = uAh + 2 * GMAT;
        const uint32_t uBl = uAh + 3 * GMAT;

#pragma unroll
        for (int kk = 0; kk < 2; ++kk) {
            uint32_t bh[4][2], bl[4][2];
            const int brow = wn + (lane & 7);
            const int bch = kk * 2 + ((lane >> 3) & 1);
#pragma unroll
            for (int nt = 0; nt < 4; ++nt) {
                const uint32_t off = swz(brow + nt * 8, bch);
                LDSM_X2(bh[nt], uBh + off);
                LDSM_X2(bl[nt], uBl + off);
            }
            const int arow = wm + (lane & 15);
            const int ach = kk * 2 + (lane >> 4);
#pragma unroll
            for (int mt = 0; mt < 4; ++mt) {
                const uint32_t off = swz(arow + mt * 16, ach);
                uint32_t ah[4], al[4];
                LDSM_X4(ah, uAh + off);
                LDSM_X4(al, uAl + off);
#pragma unroll
                for (int nt = 0; nt < 4; ++nt) {
                    mma_bf16(acc[mt][nt], ah, bh[nt]);
                    mma_bf16(acc[mt][nt], ah, bl[nt]);
                    mma_bf16(acc[mt][nt], al, bh[nt]);
                }
            }
        }
        __syncthreads();
    }

    if (seg == 2 && Vh != nullptr) {
        // V segment: write split bf16 directly (skip f32 round-trip)
#pragma unroll
        for (int mt = 0; mt < 4; ++mt) {
#pragma unroll
            for (int nt = 0; nt < 4; ++nt) {
                const int r0 = tm + wm + mt * 16 + (lane >> 2);
                const int cc = tn + wn + nt * 8 + 2 * (lane & 3);
#pragma unroll
                for (int half = 0; half < 2; ++half) {
                    const float v0 = acc[mt][nt][2 * half];
                    const float v1 = acc[mt][nt][2 * half + 1];
                    const uint32_t hh = pack_bf16x2(v0, v1);
                    const uint32_t ll = pack_bf16x2(v0 - bf_lo(hh), v1 - bf_hi(hh));
                    const size_t o = (size_t)(r0 + 8 * half) * D_MODEL + cc;
                    *(uint32_t*)&Vh[o] = hh;
                    *(uint32_t*)&Vl[o] = ll;
                }
            }
        }
    } else {
        float* C = (seg == 1) ? C1 : C0;
#pragma unroll
        for (int mt = 0; mt < 4; ++mt) {
#pragma unroll
            for (int nt = 0; nt < 4; ++nt) {
                const int r0 = tm + wm + mt * 16 + (lane >> 2);
                const int cc = tn + wn + nt * 8 + 2 * (lane & 3);
                *(float2*)&C[(size_t)r0 * D_MODEL + cc] = make_float2(acc[mt][nt][0], acc[mt][nt][1]);
                *(float2*)&C[(size_t)(r0 + 8) * D_MODEL + cc] = make_float2(acc[mt][nt][2], acc[mt][nt][3]);
            }
        }
    }
}

// ---------------------------------------------------------------------------
// Fused per-head RMSNorm + RoPE -> split bf16 outputs
// ---------------------------------------------------------------------------
__global__ __launch_bounds__(256) void rmsrope_kernel(const float* __restrict__ w_q,
                                                      const float* __restrict__ w_k) {
    const int gw   = (blockIdx.x * blockDim.x + threadIdx.x) >> 5;
    const int lane = threadIdx.x & 31;
    const float* src = (blockIdx.y == 0) ? g_q : g_k;
    const float* w   = (blockIdx.y == 0) ? w_q : w_k;
    __nv_bfloat16* oh = (blockIdx.y == 0) ? g_qh : g_kh;
    __nv_bfloat16* ol = (blockIdx.y == 0) ? g_ql : g_kl;
    const int t = (gw / N_HEADS) % SEQ;
    const size_t base = (size_t)gw * HD;

    float x1 = src[base + lane];
    float x2 = src[base + lane + 32];
    float ss = x1 * x1 + x2 * x2;
#pragma unroll
    for (int o = 16; o; o >>= 1) ss += __shfl_xor_sync(0xffffffffu, ss, o);
    const float r = rsqrtf(ss * (1.0f / 64.0f) + 1e-6f);
    x1 *= r * w[lane];
    x2 *= r * w[lane + 32];
    const float inv = exp2f(-(float)lane * 0.41524101186091903f);
    const float ang = (float)t * inv;
    float sn, cs;
    sincosf(ang, &sn, &cs);
    const float y1 = x1 * cs - x2 * sn;
    const float y2 = x2 * cs + x1 * sn;

    __nv_bfloat16 h1 = __float2bfloat16_rn(y1);
    __nv_bfloat16 h2 = __float2bfloat16_rn(y2);
    oh[base + lane]      = h1;
    oh[base + lane + 32] = h2;
    ol[base + lane]      = __float2bfloat16_rn(y1 - __bfloat162float(h1));
    ol[base + lane + 32] = __float2bfloat16_rn(y2 - __bfloat162float(h2));
}

// ---------------------------------------------------------------------------
// HMMA flash attention, split-bf16, SW128 smem, HYBRID MUFU+poly softmax.
// Scores kept in base-2 domain (log2e folded into scale).
// ---------------------------------------------------------------------------
#define AQMAT 16384                   // q matrix tile: 128 rows x 128B
#define AKMAT 8192                    // kv matrix tile: 64 rows x 128B
#define AKSTG (4 * AKMAT)             // Kh, Kl, Vh, Vl per stage
#define ATT_SMEM (2 * AQMAT + 2 * AKSTG)   // 98304 bytes

__global__ __launch_bounds__(256) void attn_hmma() {
    extern __shared__ char smA[];
    const uint32_t u0  = smem_to_u32(smA);
    const uint32_t uQh = u0;
    const uint32_t uQl = u0 + AQMAT;

    const int tid = threadIdx.x, warp = tid >> 5, lane = tid & 31;
    const int qt = (int)(gridDim.x - 1) - (int)blockIdx.x;   // long CTAs first
    const int h = blockIdx.y, b = blockIdx.z;
    const int wm = warp * 16;
    const size_t gq0 = ((size_t)b * SEQ + (size_t)qt * 128) * D_MODEL + h * HD;

    // ---- load q tile: 128 rows x 8 chunks = 1024 chunks, 4 per thread
#pragma unroll
    for (int c = 0; c < 4; ++c) {
        const int idx = tid + c * 256;
        const int r = idx >> 3, ch = idx & 7;
        const uint32_t sw = swzA(r, ch);
        const size_t ga = gq0 + (size_t)r * D_MODEL + ch * 8;
        cpa16(uQh + sw, g_qh + ga);
        cpa16(uQl + sw, g_ql + ga);
    }
    CP_COMMIT();

    auto load_kv = [&](int s, int kb) {
        const uint32_t ub = u0 + 2 * AQMAT + s * AKSTG;
#pragma unroll
        for (int c = 0; c < 2; ++c) {
            const int idx = tid * 2 + c;             // 512 chunks = 64 rows x 8
            const int r = idx >> 3, ch = idx & 7;
            const uint32_t sw = swzA(r, ch);
            const size_t ga = ((size_t)b * SEQ + (size_t)kb * 64 + r) * D_MODEL + h * HD + ch * 8;
            cpa16(ub + sw,             g_kh + ga);
            cpa16(ub + AKMAT + sw,     g_kl + ga);
            cpa16(ub + 2 * AKMAT + sw, g_vh + ga);
            cpa16(ub + 3 * AKMAT + sw, g_vl + ga);
        }
        CP_COMMIT();
    };

    load_kv(0, 0);
    asm volatile("cp.async.wait_group 0;" ::: "memory");
    __syncthreads();

    // ---- q fragments (A, m16k16), once
    uint32_t qfh[4][4], qfl[4][4];
    {
        const int arow = wm + (lane & 15);
#pragma unroll
        for (int ks = 0; ks < 4; ++ks) {
            const uint32_t off = swzA(arow, ks * 2 + (lane >> 4));
            LDSM_X4(qfh[ks], uQh + off);
            LDSM_X4(qfl[ks], uQl + off);
        }
    }

    float acc[8][4] = {};
    float m0 = -1e30f, m1 = -1e30f, l0 = 0.f, l1 = 0.f;
    const int nkb = 2 * qt + 2;
    const int qrow0 = qt * 128 + wm;

    for (int kb = 0; kb < nkb; ++kb) {
        const int s = kb & 1;
        if (kb + 1 < nkb) {
            load_kv(s ^ 1, kb + 1);
            asm volatile("cp.async.wait_group 1;" ::: "memory");
        } else {
            asm volatile("cp.async.wait_group 0;" ::: "memory");
        }
        __syncthreads();

        const bool active = (kb * 64 <= qrow0 + 15);
        if (active) {
            const uint32_t uKh = u0 + 2 * AQMAT + s * AKSTG;
            const uint32_t uKl = uKh + AKMAT;
            const uint32_t uVh = uKh + 2 * AKMAT;
            const uint32_t uVl = uKh + 3 * AKMAT;

            // ---- S = q k^T (3-term split)
            float sc[8][4] = {};
#pragma unroll
            for (int ks = 0; ks < 4; ++ks) {
                const int bch = ks * 2 + ((lane >> 3) & 1);
                const int brow = (lane & 7) + ((lane >> 4) << 3);
#pragma unroll
                for (int np = 0; np < 4; ++np) {
                    const uint32_t boff = swzA(np * 16 + brow, bch);
                    uint32_t bh[4], bl[4];
                    LDSM_X4(bh, uKh + boff);
                    LDSM_X4(bl, uKl + boff);
                    mma_bf16(sc[2 * np],     qfh[ks], &bh[0]);
                    mma_bf16(sc[2 * np],     qfh[ks], &bl[0]);
                    mma_bf16(sc[2 * np],     qfl[ks], &bh[0]);
                    mma_bf16(sc[2 * np + 1], qfh[ks], &bh[2]);
                    mma_bf16(sc[2 * np + 1], qfh[ks], &bl[2]);
                    mma_bf16(sc[2 * np + 1], qfl[ks], &bh[2]);
                }
            }

            // ---- scale (base-2 domain) + mask + online softmax
            const float SCL2 = 0.18033688011112042f;   // 0.125 * log2(e)
            const bool domask = (kb * 64 + 63 > qrow0);
            const int r0 = qrow0 + (lane >> 2);
            float mt0 = -1e30f, mt1 = -1e30f;
#pragma unroll
            for (int nt = 0; nt < 8; ++nt) {
#pragma unroll
                for (int j = 0; j < 4; ++j) sc[nt][j] *= SCL2;
                if (domask) {
                    const int colb = kb * 64 + nt * 8 + 2 * (lane & 3);
                    if (colb     > r0)     sc[nt][0] = -1e30f;
                    if (colb + 1 > r0)     sc[nt][1] = -1e30f;
                    if (colb     > r0 + 8) sc[nt][2] = -1e30f;
                    if (colb + 1 > r0 + 8) sc[nt][3] = -1e30f;
                }
                mt0 = fmaxf(mt0, fmaxf(sc[nt][0], sc[nt][1]));
                mt1 = fmaxf(mt1, fmaxf(sc[nt][2], sc[nt][3]));
            }
            mt0 = fmaxf(mt0, __shfl_xor_sync(0xffffffffu, mt0, 1));
            mt0 = fmaxf(mt0, __shfl_xor_sync(0xffffffffu, mt0, 2));
            mt1 = fmaxf(mt1, __shfl_xor_sync(0xffffffffu, mt1, 1));
            mt1 = fmaxf(mt1, __shfl_xor_sync(0xffffffffu, mt1, 2));
            const float mn0 = fmaxf(m0, mt0), mn1 = fmaxf(m1, mt1);
            const float a0 = exp2f(m0 - mn0), a1 = exp2f(m1 - mn1);
            m0 = mn0; m1 = mn1;

            float s0 = 0.f, s1 = 0.f;
            uint32_t ph[4][4], pl[4][4];
#pragma unroll
            for (int nt = 0; nt < 8; ++nt) {
                float p0, p1, p2, p3;
                if (nt & 1) {   // poly half: FMA/ALU pipes
                    p0 = fexp2(sc[nt][0] - mn0);
                    p1 = fexp2(sc[nt][1] - mn0);
                    p2 = fexp2(sc[nt][2] - mn1);
                    p3 = fexp2(sc[nt][3] - mn1);
                } else {        // MUFU half
                    p0 = exp2f(sc[nt][0] - mn0);
                    p1 = exp2f(sc[nt][1] - mn0);
                    p2 = exp2f(sc[nt][2] - mn1);
                    p3 = exp2f(sc[nt][3] - mn1);
                }
                s0 += p0 + p1;
                s1 += p2 + p3;
                const uint32_t hA = pack_bf16x2(p0, p1);
                const uint32_t hB = pack_bf16x2(p2, p3);
                const uint32_t lA = pack_bf16x2(p0 - bf_lo(hA), p1 - bf_hi(hA));
                const uint32_t lB = pack_bf16x2(p2 - bf_lo(hB), p3 - bf_hi(hB));
                const int ks = nt >> 1, pos = (nt & 1) * 2;
                ph[ks][pos] = hA; ph[ks][pos + 1] = hB;
                pl[ks][pos] = lA; pl[ks][pos + 1] = lB;
            }
            s0 += __shfl_xor_sync(0xffffffffu, s0, 1);
            s0 += __shfl_xor_sync(0xffffffffu, s0, 2);
            s1 += __shfl_xor_sync(0xffffffffu, s1, 1);
            s1 += __shfl_xor_sync(0xffffffffu, s1, 2);
            l0 = l0 * a0 + s0;
            l1 = l1 * a1 + s1;
#pragma unroll
            for (int nt = 0; nt < 8; ++nt) {
                acc[nt][0] *= a0; acc[nt][1] *= a0;
                acc[nt][2] *= a1; acc[nt][3] *= a1;
            }

            // ---- O += P V (3-term split, V via ldmatrix.trans)
#pragma unroll
            for (int ks = 0; ks < 4; ++ks) {
                const int vrow = ks * 16 + (lane & 7) + (((lane >> 3) & 1) << 3);
#pragma unroll
                for (int np = 0; np < 4; ++np) {
                    const uint32_t voff = swzA(vrow, np * 2 + (lane >> 4));
                    uint32_t vh4[4], vl4[4];
                    LDSM_X4_T(vh4, uVh + voff);
                    LDSM_X4_T(vl4, uVl + voff);
                    mma_bf16(acc[2 * np],     ph[ks], &vh4[0]);
                    mma_bf16(acc[2 * np],     ph[ks], &vl4[0]);
                    mma_bf16(acc[2 * np],     pl[ks], &vh4[0]);
                    mma_bf16(acc[2 * np + 1], ph[ks], &vh4[2]);
                    mma_bf16(acc[2 * np + 1], ph[ks], &vl4[2]);
                    mma_bf16(acc[2 * np + 1], pl[ks], &vh4[2]);
                }
            }
        }
        __syncthreads();
    }

    // ---- epilogue: normalize, split to bf16 hi/lo, write O-proj A buffers
    const float i0 = 1.0f / l0, i1 = 1.0f / l1;
    const size_t gr0 = ((size_t)b * SEQ + qrow0 + (lane >> 2)) * D_MODEL + h * HD + 2 * (lane & 3);
#pragma unroll
    for (int nt = 0; nt < 8; ++nt) {
        const float o0 = acc[nt][0] * i0, o1 = acc[nt][1] * i0;
        const float o2 = acc[nt][2] * i1, o3 = acc[nt][3] * i1;
        const uint32_t hA = pack_bf16x2(o0, o1);
        const uint32_t hB = pack_bf16x2(o2, o3);
        const uint32_t lA = pack_bf16x2(o0 - bf_lo(hA), o1 - bf_hi(hA));
        const uint32_t lB = pack_bf16x2(o2 - bf_lo(hB), o3 - bf_hi(hB));
        *(uint32_t*)&g_ah[gr0 + nt * 8]               = hA;
        *(uint32_t*)&g_al[gr0 + nt * 8]               = lA;
        *(uint32_t*)&g_ah[gr0 + 8 * D_MODEL + nt * 8] = hB;
        *(uint32_t*)&g_al[gr0 + 8 * D_MODEL + nt * 8] = lB;
    }
}

// ---------------------------------------------------------------------------
extern "C" void kernel_launch(void* const* d_in, const int* in_sizes, int n_in,
                              void* d_out, int out_size) {
    const float* x  = (const float*)d_in[0];
    const float* Wq = (const float*)d_in[1];
    const float* Wk = (const float*)d_in[2];
    const float* Wv = (const float*)d_in[3];
    const float* Wo = (const float*)d_in[4];
    const float* qw = (const float*)d_in[5];
    const float* kw = (const float*)d_in[6];
    float* out = (float*)d_out;

    float *qb, *kb;
    __nv_bfloat16 *xh, *xl, *ah, *al, *vh, *vl, *wth, *wtl;
    cudaGetSymbolAddress((void**)&qb, g_q);
    cudaGetSymbolAddress((void**)&kb, g_k);
    cudaGetSymbolAddress((void**)&xh, g_xh);
    cudaGetSymbolAddress((void**)&xl, g_xl);
    cudaGetSymbolAddress((void**)&ah, g_ah);
    cudaGetSymbolAddress((void**)&al, g_al);
    cudaGetSymbolAddress((void**)&vh, g_vh);
    cudaGetSymbolAddress((void**)&vl, g_vl);
    cudaGetSymbolAddress((void**)&wth, g_wth);
    cudaGetSymbolAddress((void**)&wtl, g_wtl);

    const int NEL = M_ROWS * D_MODEL;
    const size_t WSZ = (size_t)D_MODEL * D_MODEL;

    split_kernel<<<NEL / (256 * 4), 256>>>(x, xh, xl);
    wsplit_kernel<<<dim3(32, 32, 4), 256>>>(Wq, Wk, Wv, Wo);

    cudaFuncSetAttribute(hmma_gemm, cudaFuncAttributeMaxDynamicSharedMemorySize, GEMM_SMEM);
    // fused QKV: N = 3072; V segment writes split bf16 directly
    hmma_gemm<<<dim3(3 * D_MODEL / 128, M_ROWS / 128), 256, GEMM_SMEM>>>(
        xh, xl, wth, wtl, qb, kb, vh, vl);

    rmsrope_kernel<<<dim3((M_ROWS * N_HEADS) / 8, 2), 256>>>(qw, kw);

    cudaFuncSetAttribute(attn_hmma, cudaFuncAttributeMaxDynamicSharedMemorySize, ATT_SMEM);
    attn_hmma<<<dim3(SEQ / 128, N_HEADS, BATCH), 256, ATT_SMEM>>>();

    // O projection (f32 out)
    hmma_gemm<<<dim3(D_MODEL / 128, M_ROWS / 128), 256, GEMM_SMEM>>>(
        ah, al, wth + 3 * WSZ, wtl + 3 * WSZ, out, out, nullptr, nullptr);
}

// round 8
// speedup vs baseline: 2.4483x; 1.3527x over previous
#include <cuda_runtime.h>
#include <cuda_fp16.h>
#include <math.h>
#include <cstdint>

#define D_MODEL 1024
#define N_HEADS 16
#define HD      64
#define SEQ     2048
#define BATCH   2
#define M_ROWS  (BATCH * SEQ)   // 4096

// ---------------- scratch (__device__ globals; no allocs allowed) ----------
__device__ float g_q[M_ROWS * D_MODEL];
__device__ float g_k[M_ROWS * D_MODEL];
__device__ __half g_xh[M_ROWS * D_MODEL];          // x plain fp16
__device__ __half g_ah[M_ROWS * D_MODEL];          // attention out plain fp16
__device__ __half g_qh[M_ROWS * D_MODEL];          // q plain fp16
__device__ __half g_kh[M_ROWS * D_MODEL];          // k split hi
__device__ __half g_kl[M_ROWS * D_MODEL];          // k split lo
__device__ __half g_vh[M_ROWS * D_MODEL];          // v split hi
__device__ __half g_vl[M_ROWS * D_MODEL];          // v split lo
__device__ __half g_wth[4 * D_MODEL * D_MODEL];    // W^T split hi, [w][n][k]
__device__ __half g_wtl[4 * D_MODEL * D_MODEL];    // W^T split lo

// ---------------- PTX helpers (portable: sm_80+ features only) -------------
__device__ __forceinline__ uint32_t smem_to_u32(const void* p) {
    uint32_t a;
    asm("{ .reg .u64 t; cvta.to.shared.u64 t, %1; cvt.u32.u64 %0, t; }" : "=r"(a) : "l"(p));
    return a;
}
__device__ __forceinline__ void cpa16(uint32_t d, const void* s) {
    asm volatile("cp.async.cg.shared.global [%0], [%1], 16;" :: "r"(d), "l"(s));
}
#define CP_COMMIT() asm volatile("cp.async.commit_group;" ::: "memory")
#define LDSM_X4(r, a) \
    asm volatile("ldmatrix.sync.aligned.m8n8.x4.shared.b16 {%0,%1,%2,%3}, [%4];" \
                 : "=r"((r)[0]), "=r"((r)[1]), "=r"((r)[2]), "=r"((r)[3]) : "r"(a))
#define LDSM_X4_T(r, a) \
    asm volatile("ldmatrix.sync.aligned.m8n8.x4.trans.shared.b16 {%0,%1,%2,%3}, [%4];" \
                 : "=r"((r)[0]), "=r"((r)[1]), "=r"((r)[2]), "=r"((r)[3]) : "r"(a))
#define LDSM_X2(r, a) \
    asm volatile("ldmatrix.sync.aligned.m8n8.x2.shared.b16 {%0,%1}, [%2];" \
                 : "=r"((r)[0]), "=r"((r)[1]) : "r"(a))
__device__ __forceinline__ void mma_f16(float* c, const uint32_t* a, const uint32_t* b) {
    asm volatile("mma.sync.aligned.m16n8k16.row.col.f32.f16.f16.f32 "
                 "{%0,%1,%2,%3}, {%4,%5,%6,%7}, {%8,%9}, {%0,%1,%2,%3};"
                 : "+f"(c[0]), "+f"(c[1]), "+f"(c[2]), "+f"(c[3])
                 : "r"(a[0]), "r"(a[1]), "r"(a[2]), "r"(a[3]), "r"(b[0]), "r"(b[1]));
}
__device__ __forceinline__ uint32_t pack_h2(float lo, float hi) {
    __half2 t = __halves2half2(__float2half_rn(lo), __float2half_rn(hi));
    return *(uint32_t*)&t;
}

// GEMM tiles: 64B logical rows (4 chunks); 128B line = 2 rows.
__device__ __forceinline__ uint32_t swz(int r, int ch) {
    return (uint32_t)(((r >> 1) << 7) + (((((r & 1) << 2) + ch) ^ ((r >> 1) & 7)) << 4));
}
// Attention tiles: 128B rows (8 chunks), SW128 atom. ch in 0..7.
__device__ __forceinline__ uint32_t swzA(int r, int ch) {
    return (uint32_t)((r << 7) + ((ch ^ (r & 7)) << 4));
}

// 2^y on FMA/ALU pipes, y <= 0 (poly half of the hybrid softmax)
__device__ __forceinline__ float fexp2(float y) {
    y = fmaxf(y, -120.0f);
    const float z = y + 12582912.0f;              // round-to-nearest int
    const int   n = __float_as_int(z) - 0x4B400000;
    const float f = y - (z - 12582912.0f);        // in [-0.5, 0.5]
    float p = 0.0013333558f;
    p = fmaf(p, f, 0.009618129f);
    p = fmaf(p, f, 0.05550411f);
    p = fmaf(p, f, 0.24022651f);
    p = fmaf(p, f, 0.69314718f);
    p = fmaf(p, f, 1.0f);
    return p * __int_as_float((n + 127) << 23);
}

// ---------------------------------------------------------------------------
// cvt: fp32 -> fp16 plain, elementwise (for x)
// ---------------------------------------------------------------------------
__global__ __launch_bounds__(256) void cvt_kernel(const float* __restrict__ src,
                                                  __half* __restrict__ dst) {
    const int i = (blockIdx.x * 256 + threadIdx.x) * 4;
    float4 v = *(const float4*)(src + i);
    __half2* D = (__half2*)(dst + i);
    D[0] = __halves2half2(__float2half_rn(v.x), __float2half_rn(v.y));
    D[1] = __halves2half2(__float2half_rn(v.z), __float2half_rn(v.w));
}

// ---------------------------------------------------------------------------
// weight transpose + fp16 split
// ---------------------------------------------------------------------------
__global__ __launch_bounds__(256) void wsplit_kernel(const float* __restrict__ w0,
                                                     const float* __restrict__ w1,
                                                     const float* __restrict__ w2,
                                                     const float* __restrict__ w3) {
    __shared__ float t[32][33];
    const float* W = (blockIdx.z == 0) ? w0 : (blockIdx.z == 1) ? w1 : (blockIdx.z == 2) ? w2 : w3;
    const int nb = blockIdx.x * 32, kb = blockIdx.y * 32;
    const int tx = threadIdx.x & 31, ty = threadIdx.x >> 5;
#pragma unroll
    for (int i = 0; i < 32; i += 8)
        t[ty + i][tx] = W[(size_t)(kb + ty + i) * D_MODEL + nb + tx];
    __syncthreads();
    const size_t base = (size_t)blockIdx.z * D_MODEL * D_MODEL;
#pragma unroll
    for (int i = 0; i < 32; i += 8) {
        float v = t[tx][ty + i];
        __half h = __float2half_rn(v);
        size_t o = base + (size_t)(nb + ty + i) * D_MODEL + kb + tx;
        g_wth[o] = h;
        g_wtl[o] = __float2half_rn(v - __half2float(h));
    }
}

// ---------------------------------------------------------------------------
// HMMA 2-term fp16 GEMM: C = A_plain @ (Bh + Bl)^T. Swizzled smem, 2 CTAs/SM.
// QKV fused: N=3072; seg 0/1 -> f32 C0/C1; seg 2 -> split fp16 Vh/Vl.
// ---------------------------------------------------------------------------
#define GMAT 8192                     // bytes per matrix tile (128 rows x 64B)
#define GSTAGE (3 * GMAT)             // A, Bh, Bl
#define GEMM_SMEM (2 * GSTAGE)        // 49152 bytes

__global__ __launch_bounds__(256, 2) void hmma_gemm(const __half* __restrict__ A,
                                                    const __half* __restrict__ Bh,
                                                    const __half* __restrict__ Bl,
                                                    float* __restrict__ C0,
                                                    float* __restrict__ C1,
                                                    __half* __restrict__ Vh,
                                                    __half* __restrict__ Vl) {
    extern __shared__ char smg[];
    const uint32_t u0 = smem_to_u32(smg);

    const int tid = threadIdx.x, warp = tid >> 5, lane = tid & 31;
    const int tm = blockIdx.y * 128;
    const int tnG = blockIdx.x * 128;
    const int tn = tnG & 1023;
    const int seg = tnG >> 10;
    const int wm = (warp >> 2) * 64, wn = (warp & 3) * 32;

    const int c0 = tid * 2, c1 = tid * 2 + 1;
    const int r0c = c0 >> 2, h0c = c0 & 3;
    const int r1c = c1 >> 2, h1c = c1 & 3;

    auto load_stage = [&](int s, int kc) {
        const uint32_t ub = u0 + s * GSTAGE;
        {
            const uint32_t sw = swz(r0c, h0c);
            const size_t ga = (size_t)(tm + r0c) * D_MODEL + kc + h0c * 8;
            const size_t gb = (size_t)(tnG + r0c) * D_MODEL + kc + h0c * 8;
            cpa16(ub + sw,            A + ga);
            cpa16(ub + GMAT + sw,     Bh + gb);
            cpa16(ub + 2 * GMAT + sw, Bl + gb);
        }
        {
            const uint32_t sw = swz(r1c, h1c);
            const size_t ga = (size_t)(tm + r1c) * D_MODEL + kc + h1c * 8;
            const size_t gb = (size_t)(tnG + r1c) * D_MODEL + kc + h1c * 8;
            cpa16(ub + sw,            A + ga);
            cpa16(ub + GMAT + sw,     Bh + gb);
            cpa16(ub + 2 * GMAT + sw, Bl + gb);
        }
        CP_COMMIT();
    };

    float acc[4][4][4] = {};

    load_stage(0, 0);
    const int NKB = D_MODEL / 32;
    for (int kb = 0; kb < NKB; ++kb) {
        const int s = kb & 1;
        if (kb + 1 < NKB) {
            load_stage(s ^ 1, (kb + 1) * 32);
            asm volatile("cp.async.wait_group 1;" ::: "memory");
        } else {
            asm volatile("cp.async.wait_group 0;" ::: "memory");
        }
        __syncthreads();
        const uint32_t uA  = u0 + s * GSTAGE;
        const uint32_t uBh = uA + GMAT;
        const uint32_t uBl = uA + 2 * GMAT;

#pragma unroll
        for (int kk = 0; kk < 2; ++kk) {
            uint32_t bh[4][2], bl[4][2];
            const int brow = wn + (lane & 7);
            const int bch = kk * 2 + ((lane >> 3) & 1);
#pragma unroll
            for (int nt = 0; nt < 4; ++nt) {
                const uint32_t off = swz(brow + nt * 8, bch);
                LDSM_X2(bh[nt], uBh + off);
                LDSM_X2(bl[nt], uBl + off);
            }
            const int arow = wm + (lane & 15);
            const int ach = kk * 2 + (lane >> 4);
#pragma unroll
            for (int mt = 0; mt < 4; ++mt) {
                const uint32_t off = swz(arow + mt * 16, ach);
                uint32_t a4[4];
                LDSM_X4(a4, uA + off);
#pragma unroll
                for (int nt = 0; nt < 4; ++nt) {
                    mma_f16(acc[mt][nt], a4, bh[nt]);
                    mma_f16(acc[mt][nt], a4, bl[nt]);
                }
            }
        }
        __syncthreads();
    }

    if (seg == 2 && Vh != nullptr) {
#pragma unroll
        for (int mt = 0; mt < 4; ++mt) {
#pragma unroll
            for (int nt = 0; nt < 4; ++nt) {
                const int r0 = tm + wm + mt * 16 + (lane >> 2);
                const int cc = tn + wn + nt * 8 + 2 * (lane & 3);
#pragma unroll
                for (int half = 0; half < 2; ++half) {
                    const float v0 = acc[mt][nt][2 * half];
                    const float v1 = acc[mt][nt][2 * half + 1];
                    const __half h0 = __float2half_rn(v0), h1 = __float2half_rn(v1);
                    const size_t o = (size_t)(r0 + 8 * half) * D_MODEL + cc;
                    __half2 hh = __halves2half2(h0, h1);
                    __half2 ll = __halves2half2(__float2half_rn(v0 - __half2float(h0)),
                                                __float2half_rn(v1 - __half2float(h1)));
                    *(__half2*)&Vh[o] = hh;
                    *(__half2*)&Vl[o] = ll;
                }
            }
        }
    } else {
        float* C = (seg == 1) ? C1 : C0;
#pragma unroll
        for (int mt = 0; mt < 4; ++mt) {
#pragma unroll
            for (int nt = 0; nt < 4; ++nt) {
                const int r0 = tm + wm + mt * 16 + (lane >> 2);
                const int cc = tn + wn + nt * 8 + 2 * (lane & 3);
                *(float2*)&C[(size_t)r0 * D_MODEL + cc] = make_float2(acc[mt][nt][0], acc[mt][nt][1]);
                *(float2*)&C[(size_t)(r0 + 8) * D_MODEL + cc] = make_float2(acc[mt][nt][2], acc[mt][nt][3]);
            }
        }
    }
}

// ---------------------------------------------------------------------------
// Fused per-head RMSNorm + RoPE -> q plain fp16, k split fp16
// ---------------------------------------------------------------------------
__global__ __launch_bounds__(256) void rmsrope_kernel(const float* __restrict__ w_q,
                                                      const float* __restrict__ w_k) {
    const int gw   = (blockIdx.x * blockDim.x + threadIdx.x) >> 5;
    const int lane = threadIdx.x & 31;
    const bool isq = (blockIdx.y == 0);
    const float* src = isq ? g_q : g_k;
    const float* w   = isq ? w_q : w_k;
    const int t = (gw / N_HEADS) % SEQ;
    const size_t base = (size_t)gw * HD;

    float x1 = src[base + lane];
    float x2 = src[base + lane + 32];
    float ss = x1 * x1 + x2 * x2;
#pragma unroll
    for (int o = 16; o; o >>= 1) ss += __shfl_xor_sync(0xffffffffu, ss, o);
    const float r = rsqrtf(ss * (1.0f / 64.0f) + 1e-6f);
    x1 *= r * w[lane];
    x2 *= r * w[lane + 32];
    const float inv = exp2f(-(float)lane * 0.41524101186091903f);
    const float ang = (float)t * inv;
    float sn, cs;
    sincosf(ang, &sn, &cs);
    const float y1 = x1 * cs - x2 * sn;
    const float y2 = x2 * cs + x1 * sn;

    if (isq) {
        g_qh[base + lane]      = __float2half_rn(y1);
        g_qh[base + lane + 32] = __float2half_rn(y2);
    } else {
        const __half h1 = __float2half_rn(y1), h2 = __float2half_rn(y2);
        g_kh[base + lane]      = h1;
        g_kh[base + lane + 32] = h2;
        g_kl[base + lane]      = __float2half_rn(y1 - __half2float(h1));
        g_kl[base + lane + 32] = __float2half_rn(y2 - __half2float(h2));
    }
}

// ---------------------------------------------------------------------------
// HMMA flash attention: Q plain fp16, K/V split fp16, hybrid MUFU+poly softmax.
// ---------------------------------------------------------------------------
#define AQMAT 16384                   // q tile: 128 rows x 128B
#define AKMAT 8192                    // kv tile: 64 rows x 128B
#define AKSTG (4 * AKMAT)             // Kh, Kl, Vh, Vl per stage
#define ATT_SMEM (AQMAT + 2 * AKSTG)  // 81920 bytes

__global__ __launch_bounds__(256) void attn_hmma() {
    extern __shared__ char smA[];
    const uint32_t u0  = smem_to_u32(smA);
    const uint32_t uQ = u0;

    const int tid = threadIdx.x, warp = tid >> 5, lane = tid & 31;
    const int qt = (int)(gridDim.x - 1) - (int)blockIdx.x;   // long CTAs first
    const int h = blockIdx.y, b = blockIdx.z;
    const int wm = warp * 16;
    const size_t gq0 = ((size_t)b * SEQ + (size_t)qt * 128) * D_MODEL + h * HD;

    // ---- load q tile: 128 rows x 8 chunks = 1024 chunks, 4 per thread
#pragma unroll
    for (int c = 0; c < 4; ++c) {
        const int idx = tid + c * 256;
        const int r = idx >> 3, ch = idx & 7;
        cpa16(uQ + swzA(r, ch), g_qh + gq0 + (size_t)r * D_MODEL + ch * 8);
    }
    CP_COMMIT();

    auto load_kv = [&](int s, int kb) {
        const uint32_t ub = u0 + AQMAT + s * AKSTG;
#pragma unroll
        for (int c = 0; c < 2; ++c) {
            const int idx = tid * 2 + c;             // 512 chunks = 64 rows x 8
            const int r = idx >> 3, ch = idx & 7;
            const uint32_t sw = swzA(r, ch);
            const size_t ga = ((size_t)b * SEQ + (size_t)kb * 64 + r) * D_MODEL + h * HD + ch * 8;
            cpa16(ub + sw,             g_kh + ga);
            cpa16(ub + AKMAT + sw,     g_kl + ga);
            cpa16(ub + 2 * AKMAT + sw, g_vh + ga);
            cpa16(ub + 3 * AKMAT + sw, g_vl + ga);
        }
        CP_COMMIT();
    };

    load_kv(0, 0);
    asm volatile("cp.async.wait_group 0;" ::: "memory");
    __syncthreads();

    // ---- q fragments (A, m16k16), once
    uint32_t qf[4][4];
    {
        const int arow = wm + (lane & 15);
#pragma unroll
        for (int ks = 0; ks < 4; ++ks)
            LDSM_X4(qf[ks], uQ + swzA(arow, ks * 2 + (lane >> 4)));
    }

    float acc[8][4] = {};
    float m0 = -1e30f, m1 = -1e30f, l0 = 0.f, l1 = 0.f;
    const int nkb = 2 * qt + 2;
    const int qrow0 = qt * 128 + wm;

    for (int kb = 0; kb < nkb; ++kb) {
        const int s = kb & 1;
        if (kb + 1 < nkb) {
            load_kv(s ^ 1, kb + 1);
            asm volatile("cp.async.wait_group 1;" ::: "memory");
        } else {
            asm volatile("cp.async.wait_group 0;" ::: "memory");
        }
        __syncthreads();

        const bool active = (kb * 64 <= qrow0 + 15);
        if (active) {
            const uint32_t uKh = u0 + AQMAT + s * AKSTG;
            const uint32_t uKl = uKh + AKMAT;
            const uint32_t uVh = uKh + 2 * AKMAT;
            const uint32_t uVl = uKh + 3 * AKMAT;

            // ---- S = q (kh + kl)^T (2-term)
            float sc[8][4] = {};
#pragma unroll
            for (int ks = 0; ks < 4; ++ks) {
                const int bch = ks * 2 + ((lane >> 3) & 1);
                const int brow = (lane & 7) + ((lane >> 4) << 3);
#pragma unroll
                for (int np = 0; np < 4; ++np) {
                    const uint32_t boff = swzA(np * 16 + brow, bch);
                    uint32_t bh[4], bl[4];
                    LDSM_X4(bh, uKh + boff);
                    LDSM_X4(bl, uKl + boff);
                    mma_f16(sc[2 * np],     qf[ks], &bh[0]);
                    mma_f16(sc[2 * np],     qf[ks], &bl[0]);
                    mma_f16(sc[2 * np + 1], qf[ks], &bh[2]);
                    mma_f16(sc[2 * np + 1], qf[ks], &bl[2]);
                }
            }

            // ---- scale (base-2 domain) + mask + online softmax
            const float SCL2 = 0.18033688011112042f;   // 0.125 * log2(e)
            const bool domask = (kb * 64 + 63 > qrow0);
            const int r0 = qrow0 + (lane >> 2);
            float mt0 = -1e30f, mt1 = -1e30f;
#pragma unroll
            for (int nt = 0; nt < 8; ++nt) {
#pragma unroll
                for (int j = 0; j < 4; ++j) sc[nt][j] *= SCL2;
                if (domask) {
                    const int colb = kb * 64 + nt * 8 + 2 * (lane & 3);
                    if (colb     > r0)     sc[nt][0] = -1e30f;
                    if (colb + 1 > r0)     sc[nt][1] = -1e30f;
                    if (colb     > r0 + 8) sc[nt][2] = -1e30f;
                    if (colb + 1 > r0 + 8) sc[nt][3] = -1e30f;
                }
                mt0 = fmaxf(mt0, fmaxf(sc[nt][0], sc[nt][1]));
                mt1 = fmaxf(mt1, fmaxf(sc[nt][2], sc[nt][3]));
            }
            mt0 = fmaxf(mt0, __shfl_xor_sync(0xffffffffu, mt0, 1));
            mt0 = fmaxf(mt0, __shfl_xor_sync(0xffffffffu, mt0, 2));
            mt1 = fmaxf(mt1, __shfl_xor_sync(0xffffffffu, mt1, 1));
            mt1 = fmaxf(mt1, __shfl_xor_sync(0xffffffffu, mt1, 2));
            const float mn0 = fmaxf(m0, mt0), mn1 = fmaxf(m1, mt1);
            const float a0 = exp2f(m0 - mn0), a1 = exp2f(m1 - mn1);
            m0 = mn0; m1 = mn1;

            float s0 = 0.f, s1 = 0.f;
            uint32_t ph[4][4];
#pragma unroll
            for (int nt = 0; nt < 8; ++nt) {
                float p0, p1, p2, p3;
                if (nt & 1) {   // poly half: FMA/ALU pipes
                    p0 = fexp2(sc[nt][0] - mn0);
                    p1 = fexp2(sc[nt][1] - mn0);
                    p2 = fexp2(sc[nt][2] - mn1);
                    p3 = fexp2(sc[nt][3] - mn1);
                } else {        // MUFU half
                    p0 = exp2f(sc[nt][0] - mn0);
                    p1 = exp2f(sc[nt][1] - mn0);
                    p2 = exp2f(sc[nt][2] - mn1);
                    p3 = exp2f(sc[nt][3] - mn1);
                }
                s0 += p0 + p1;
                s1 += p2 + p3;
                const int ks = nt >> 1, pos = (nt & 1) * 2;
                ph[ks][pos]     = pack_h2(p0, p1);
                ph[ks][pos + 1] = pack_h2(p2, p3);
            }
            s0 += __shfl_xor_sync(0xffffffffu, s0, 1);
            s0 += __shfl_xor_sync(0xffffffffu, s0, 2);
            s1 += __shfl_xor_sync(0xffffffffu, s1, 1);
            s1 += __shfl_xor_sync(0xffffffffu, s1, 2);
            l0 = l0 * a0 + s0;
            l1 = l1 * a1 + s1;
#pragma unroll
            for (int nt = 0; nt < 8; ++nt) {
                acc[nt][0] *= a0; acc[nt][1] *= a0;
                acc[nt][2] *= a1; acc[nt][3] *= a1;
            }

            // ---- O += P (vh + vl) (2-term, V via ldmatrix.trans)
#pragma unroll
            for (int ks = 0; ks < 4; ++ks) {
                const int vrow = ks * 16 + (lane & 7) + (((lane >> 3) & 1) << 3);
#pragma unroll
                for (int np = 0; np < 4; ++np) {
                    const uint32_t voff = swzA(vrow, np * 2 + (lane >> 4));
                    uint32_t vh4[4], vl4[4];
                    LDSM_X4_T(vh4, uVh + voff);
                    LDSM_X4_T(vl4, uVl + voff);
                    mma_f16(acc[2 * np],     ph[ks], &vh4[0]);
                    mma_f16(acc[2 * np],     ph[ks], &vl4[0]);
                    mma_f16(acc[2 * np + 1], ph[ks], &vh4[2]);
                    mma_f16(acc[2 * np + 1], ph[ks], &vl4[2]);
                }
            }
        }
        __syncthreads();
    }

    // ---- epilogue: normalize, write plain fp16 O-proj A buffer
    const float i0 = 1.0f / l0, i1 = 1.0f / l1;
    const size_t gr0 = ((size_t)b * SEQ + qrow0 + (lane >> 2)) * D_MODEL + h * HD + 2 * (lane & 3);
#pragma unroll
    for (int nt = 0; nt < 8; ++nt) {
        *(uint32_t*)&g_ah[gr0 + nt * 8] =
            pack_h2(acc[nt][0] * i0, acc[nt][1] * i0);
        *(uint32_t*)&g_ah[gr0 + 8 * D_MODEL + nt * 8] =
            pack_h2(acc[nt][2] * i1, acc[nt][3] * i1);
    }
}

// ---------------------------------------------------------------------------
extern "C" void kernel_launch(void* const* d_in, const int* in_sizes, int n_in,
                              void* d_out, int out_size) {
    const float* x  = (const float*)d_in[0];
    const float* Wq = (const float*)d_in[1];
    const float* Wk = (const float*)d_in[2];
    const float* Wv = (const float*)d_in[3];
    const float* Wo = (const float*)d_in[4];
    const float* qw = (const float*)d_in[5];
    const float* kw = (const float*)d_in[6];
    float* out = (float*)d_out;

    float *qb, *kb;
    __half *xh, *ah, *vh, *vl, *wth, *wtl;
    cudaGetSymbolAddress((void**)&qb, g_q);
    cudaGetSymbolAddress((void**)&kb, g_k);
    cudaGetSymbolAddress((void**)&xh, g_xh);
    cudaGetSymbolAddress((void**)&ah, g_ah);
    cudaGetSymbolAddress((void**)&vh, g_vh);
    cudaGetSymbolAddress((void**)&vl, g_vl);
    cudaGetSymbolAddress((void**)&wth, g_wth);
    cudaGetSymbolAddress((void**)&wtl, g_wtl);

    const int NEL = M_ROWS * D_MODEL;
    const size_t WSZ = (size_t)D_MODEL * D_MODEL;

    cvt_kernel<<<NEL / (256 * 4), 256>>>(x, xh);
    wsplit_kernel<<<dim3(32, 32, 4), 256>>>(Wq, Wk, Wv, Wo);

    cudaFuncSetAttribute(hmma_gemm, cudaFuncAttributeMaxDynamicSharedMemorySize, GEMM_SMEM);
    // fused QKV: N = 3072; V segment writes split fp16 directly
    hmma_gemm<<<dim3(3 * D_MODEL / 128, M_ROWS / 128), 256, GEMM_SMEM>>>(
        xh, wth, wtl, qb, kb, vh, vl);

    rmsrope_kernel<<<dim3((M_ROWS * N_HEADS) / 8, 2), 256>>>(qw, kw);

    cudaFuncSetAttribute(attn_hmma, cudaFuncAttributeMaxDynamicSharedMemorySize, ATT_SMEM);
    attn_hmma<<<dim3(SEQ / 128, N_HEADS, BATCH), 256, ATT_SMEM>>>();

    // O projection (f32 out)
    hmma_gemm<<<dim3(D_MODEL / 128, M_ROWS / 128), 256, GEMM_SMEM>>>(
        ah, wth + 3 * WSZ, wtl + 3 * WSZ, out, out, nullptr, nullptr);
}

// round 9
// speedup vs baseline: 2.7955x; 1.1418x over previous
#include <cuda_runtime.h>
#include <cuda_fp16.h>
#include <math.h>
#include <cstdint>

#define D_MODEL 1024
#define N_HEADS 16
#define HD      64
#define SEQ     2048
#define BATCH   2
#define M_ROWS  (BATCH * SEQ)   // 4096

// ---------------- scratch (__device__ globals; no allocs allowed) ----------
__device__ __half g_x16[M_ROWS * D_MODEL];         // x plain fp16
__device__ __half g_q16[M_ROWS * D_MODEL];         // raw q (pre-rope) fp16
__device__ __half g_k16[M_ROWS * D_MODEL];         // raw k (pre-rope) fp16
__device__ __half g_qh[M_ROWS * D_MODEL];          // roped q fp16
__device__ __half g_kh[M_ROWS * D_MODEL];          // roped k fp16
__device__ __half g_vh[M_ROWS * D_MODEL];          // v fp16
__device__ __half g_ah[M_ROWS * D_MODEL];          // attention out fp16
__device__ __half g_wth[4 * D_MODEL * D_MODEL];    // W^T split hi, [w][n][k]
__device__ __half g_wtl[4 * D_MODEL * D_MODEL];    // W^T split lo

// ---------------- PTX helpers (portable: sm_80+ features only) -------------
__device__ __forceinline__ uint32_t smem_to_u32(const void* p) {
    uint32_t a;
    asm("{ .reg .u64 t; cvta.to.shared.u64 t, %1; cvt.u32.u64 %0, t; }" : "=r"(a) : "l"(p));
    return a;
}
__device__ __forceinline__ void cpa16(uint32_t d, const void* s) {
    asm volatile("cp.async.cg.shared.global [%0], [%1], 16;" :: "r"(d), "l"(s));
}
#define CP_COMMIT() asm volatile("cp.async.commit_group;" ::: "memory")
#define LDSM_X4(r, a) \
    asm volatile("ldmatrix.sync.aligned.m8n8.x4.shared.b16 {%0,%1,%2,%3}, [%4];" \
                 : "=r"((r)[0]), "=r"((r)[1]), "=r"((r)[2]), "=r"((r)[3]) : "r"(a))
#define LDSM_X4_T(r, a) \
    asm volatile("ldmatrix.sync.aligned.m8n8.x4.trans.shared.b16 {%0,%1,%2,%3}, [%4];" \
                 : "=r"((r)[0]), "=r"((r)[1]), "=r"((r)[2]), "=r"((r)[3]) : "r"(a))
#define LDSM_X2(r, a) \
    asm volatile("ldmatrix.sync.aligned.m8n8.x2.shared.b16 {%0,%1}, [%2];" \
                 : "=r"((r)[0]), "=r"((r)[1]) : "r"(a))
__device__ __forceinline__ void mma_f16(float* c, const uint32_t* a, const uint32_t* b) {
    asm volatile("mma.sync.aligned.m16n8k16.row.col.f32.f16.f16.f32 "
                 "{%0,%1,%2,%3}, {%4,%5,%6,%7}, {%8,%9}, {%0,%1,%2,%3};"
                 : "+f"(c[0]), "+f"(c[1]), "+f"(c[2]), "+f"(c[3])
                 : "r"(a[0]), "r"(a[1]), "r"(a[2]), "r"(a[3]), "r"(b[0]), "r"(b[1]));
}
__device__ __forceinline__ uint32_t pack_h2(float lo, float hi) {
    __half2 t = __halves2half2(__float2half_rn(lo), __float2half_rn(hi));
    return *(uint32_t*)&t;
}

// GEMM tiles: 64B logical rows (4 chunks); 128B line = 2 rows.
__device__ __forceinline__ uint32_t swz(int r, int ch) {
    return (uint32_t)(((r >> 1) << 7) + (((((r & 1) << 2) + ch) ^ ((r >> 1) & 7)) << 4));
}
// Attention tiles: 128B rows (8 chunks), SW128 atom. ch in 0..7.
__device__ __forceinline__ uint32_t swzA(int r, int ch) {
    return (uint32_t)((r << 7) + ((ch ^ (r & 7)) << 4));
}

// 2^y on FMA/ALU pipes, y <= 0 (poly half of the hybrid softmax)
__device__ __forceinline__ float fexp2(float y) {
    y = fmaxf(y, -120.0f);
    const float z = y + 12582912.0f;              // round-to-nearest int
    const int   n = __float_as_int(z) - 0x4B400000;
    const float f = y - (z - 12582912.0f);        // in [-0.5, 0.5]
    float p = 0.0013333558f;
    p = fmaf(p, f, 0.009618129f);
    p = fmaf(p, f, 0.05550411f);
    p = fmaf(p, f, 0.24022651f);
    p = fmaf(p, f, 0.69314718f);
    p = fmaf(p, f, 1.0f);
    return p * __int_as_float((n + 127) << 23);
}

// ---------------------------------------------------------------------------
// cvt: fp32 -> fp16 plain, elementwise (for x)
// ---------------------------------------------------------------------------
__global__ __launch_bounds__(256) void cvt_kernel(const float* __restrict__ src,
                                                  __half* __restrict__ dst) {
    const int i = (blockIdx.x * 256 + threadIdx.x) * 4;
    float4 v = *(const float4*)(src + i);
    __half2* D = (__half2*)(dst + i);
    D[0] = __halves2half2(__float2half_rn(v.x), __float2half_rn(v.y));
    D[1] = __halves2half2(__float2half_rn(v.z), __float2half_rn(v.w));
}

// ---------------------------------------------------------------------------
// weight transpose + fp16 split
// ---------------------------------------------------------------------------
__global__ __launch_bounds__(256) void wsplit_kernel(const float* __restrict__ w0,
                                                     const float* __restrict__ w1,
                                                     const float* __restrict__ w2,
                                                     const float* __restrict__ w3) {
    __shared__ float t[32][33];
    const float* W = (blockIdx.z == 0) ? w0 : (blockIdx.z == 1) ? w1 : (blockIdx.z == 2) ? w2 : w3;
    const int nb = blockIdx.x * 32, kb = blockIdx.y * 32;
    const int tx = threadIdx.x & 31, ty = threadIdx.x >> 5;
#pragma unroll
    for (int i = 0; i < 32; i += 8)
        t[ty + i][tx] = W[(size_t)(kb + ty + i) * D_MODEL + nb + tx];
    __syncthreads();
    const size_t base = (size_t)blockIdx.z * D_MODEL * D_MODEL;
#pragma unroll
    for (int i = 0; i < 32; i += 8) {
        float v = t[tx][ty + i];
        __half h = __float2half_rn(v);
        size_t o = base + (size_t)(nb + ty + i) * D_MODEL + kb + tx;
        g_wth[o] = h;
        g_wtl[o] = __float2half_rn(v - __half2float(h));
    }
}

// ---------------------------------------------------------------------------
// HMMA 2-term fp16 GEMM: C = A_plain @ (Bh + Bl)^T. Swizzled smem, 2 CTAs/SM.
// QKV fused: N=3072, per-seg fp16 outputs H0/H1/H2. O-proj: N=1024, f32 Cf.
// ---------------------------------------------------------------------------
#define GMAT 8192                     // bytes per matrix tile (128 rows x 64B)
#define GSTAGE (3 * GMAT)             // A, Bh, Bl
#define GEMM_SMEM (2 * GSTAGE)        // 49152 bytes

__global__ __launch_bounds__(256, 2) void hmma_gemm(const __half* __restrict__ A,
                                                    const __half* __restrict__ Bh,
                                                    const __half* __restrict__ Bl,
                                                    float* __restrict__ Cf,
                                                    __half* __restrict__ H0,
                                                    __half* __restrict__ H1,
                                                    __half* __restrict__ H2) {
    extern __shared__ char smg[];
    const uint32_t u0 = smem_to_u32(smg);

    const int tid = threadIdx.x, warp = tid >> 5, lane = tid & 31;
    const int tm = blockIdx.y * 128;
    const int tnG = blockIdx.x * 128;
    const int tn = tnG & 1023;
    const int seg = tnG >> 10;
    const int wm = (warp >> 2) * 64, wn = (warp & 3) * 32;

    const int c0 = tid * 2, c1 = tid * 2 + 1;
    const int r0c = c0 >> 2, h0c = c0 & 3;
    const int r1c = c1 >> 2, h1c = c1 & 3;

    auto load_stage = [&](int s, int kc) {
        const uint32_t ub = u0 + s * GSTAGE;
        {
            const uint32_t sw = swz(r0c, h0c);
            const size_t ga = (size_t)(tm + r0c) * D_MODEL + kc + h0c * 8;
            const size_t gb = (size_t)(tnG + r0c) * D_MODEL + kc + h0c * 8;
            cpa16(ub + sw,            A + ga);
            cpa16(ub + GMAT + sw,     Bh + gb);
            cpa16(ub + 2 * GMAT + sw, Bl + gb);
        }
        {
            const uint32_t sw = swz(r1c, h1c);
            const size_t ga = (size_t)(tm + r1c) * D_MODEL + kc + h1c * 8;
            const size_t gb = (size_t)(tnG + r1c) * D_MODEL + kc + h1c * 8;
            cpa16(ub + sw,            A + ga);
            cpa16(ub + GMAT + sw,     Bh + gb);
            cpa16(ub + 2 * GMAT + sw, Bl + gb);
        }
        CP_COMMIT();
    };

    float acc[4][4][4] = {};

    load_stage(0, 0);
    const int NKB = D_MODEL / 32;
    for (int kb = 0; kb < NKB; ++kb) {
        const int s = kb & 1;
        if (kb + 1 < NKB) {
            load_stage(s ^ 1, (kb + 1) * 32);
            asm volatile("cp.async.wait_group 1;" ::: "memory");
        } else {
            asm volatile("cp.async.wait_group 0;" ::: "memory");
        }
        __syncthreads();
        const uint32_t uA  = u0 + s * GSTAGE;
        const uint32_t uBh = uA + GMAT;
        const uint32_t uBl = uA + 2 * GMAT;

#pragma unroll
        for (int kk = 0; kk < 2; ++kk) {
            uint32_t bh[4][2], bl[4][2];
            const int brow = wn + (lane & 7);
            const int bch = kk * 2 + ((lane >> 3) & 1);
#pragma unroll
            for (int nt = 0; nt < 4; ++nt) {
                const uint32_t off = swz(brow + nt * 8, bch);
                LDSM_X2(bh[nt], uBh + off);
                LDSM_X2(bl[nt], uBl + off);
            }
            const int arow = wm + (lane & 15);
            const int ach = kk * 2 + (lane >> 4);
#pragma unroll
            for (int mt = 0; mt < 4; ++mt) {
                const uint32_t off = swz(arow + mt * 16, ach);
                uint32_t a4[4];
                LDSM_X4(a4, uA + off);
#pragma unroll
                for (int nt = 0; nt < 4; ++nt) {
                    mma_f16(acc[mt][nt], a4, bh[nt]);
                    mma_f16(acc[mt][nt], a4, bl[nt]);
                }
            }
        }
        __syncthreads();
    }

    __half* H = (seg == 0) ? H0 : (seg == 1) ? H1 : H2;
    if (H != nullptr) {
        // fp16 output (QKV path)
#pragma unroll
        for (int mt = 0; mt < 4; ++mt) {
#pragma unroll
            for (int nt = 0; nt < 4; ++nt) {
                const int r0 = tm + wm + mt * 16 + (lane >> 2);
                const int cc = tn + wn + nt * 8 + 2 * (lane & 3);
                *(uint32_t*)&H[(size_t)r0 * D_MODEL + cc] =
                    pack_h2(acc[mt][nt][0], acc[mt][nt][1]);
                *(uint32_t*)&H[(size_t)(r0 + 8) * D_MODEL + cc] =
                    pack_h2(acc[mt][nt][2], acc[mt][nt][3]);
            }
        }
    } else {
        // f32 output (O-proj path)
#pragma unroll
        for (int mt = 0; mt < 4; ++mt) {
#pragma unroll
            for (int nt = 0; nt < 4; ++nt) {
                const int r0 = tm + wm + mt * 16 + (lane >> 2);
                const int cc = tn + wn + nt * 8 + 2 * (lane & 3);
                *(float2*)&Cf[(size_t)r0 * D_MODEL + cc] = make_float2(acc[mt][nt][0], acc[mt][nt][1]);
                *(float2*)&Cf[(size_t)(r0 + 8) * D_MODEL + cc] = make_float2(acc[mt][nt][2], acc[mt][nt][3]);
            }
        }
    }
}

// ---------------------------------------------------------------------------
// Fused per-head RMSNorm + RoPE, fp16 in -> fp16 out
// ---------------------------------------------------------------------------
__global__ __launch_bounds__(256) void rmsrope_kernel(const float* __restrict__ w_q,
                                                      const float* __restrict__ w_k) {
    const int gw   = (blockIdx.x * blockDim.x + threadIdx.x) >> 5;
    const int lane = threadIdx.x & 31;
    const bool isq = (blockIdx.y == 0);
    const __half* src = isq ? g_q16 : g_k16;
    const float*  w   = isq ? w_q : w_k;
    __half* dst = isq ? g_qh : g_kh;
    const int t = (gw / N_HEADS) % SEQ;
    const size_t base = (size_t)gw * HD;

    float x1 = __half2float(src[base + lane]);
    float x2 = __half2float(src[base + lane + 32]);
    float ss = x1 * x1 + x2 * x2;
#pragma unroll
    for (int o = 16; o; o >>= 1) ss += __shfl_xor_sync(0xffffffffu, ss, o);
    const float r = rsqrtf(ss * (1.0f / 64.0f) + 1e-6f);
    x1 *= r * w[lane];
    x2 *= r * w[lane + 32];
    const float inv = exp2f(-(float)lane * 0.41524101186091903f);
    const float ang = (float)t * inv;
    float sn, cs;
    sincosf(ang, &sn, &cs);
    dst[base + lane]      = __float2half_rn(x1 * cs - x2 * sn);
    dst[base + lane + 32] = __float2half_rn(x2 * cs + x1 * sn);
}

// ---------------------------------------------------------------------------
// HMMA flash attention: Q, K, V all plain fp16. Hybrid MUFU+poly softmax.
// CTA = 128 q-rows x head x batch, 8 warps, K-block 64, double-buffered K/V.
// ---------------------------------------------------------------------------
#define AQMAT 16384                   // q tile: 128 rows x 128B
#define AKMAT 8192                    // kv tile: 64 rows x 128B
#define AKSTG (2 * AKMAT)             // K, V per stage
#define ATT_SMEM (AQMAT + 2 * AKSTG)  // 49152 bytes

__global__ __launch_bounds__(256) void attn_hmma() {
    extern __shared__ char smA[];
    const uint32_t u0 = smem_to_u32(smA);
    const uint32_t uQ = u0;

    const int tid = threadIdx.x, warp = tid >> 5, lane = tid & 31;
    const int qt = (int)(gridDim.x - 1) - (int)blockIdx.x;   // long CTAs first
    const int h = blockIdx.y, b = blockIdx.z;
    const int wm = warp * 16;
    const size_t gq0 = ((size_t)b * SEQ + (size_t)qt * 128) * D_MODEL + h * HD;

    // ---- load q tile: 128 rows x 8 chunks = 1024 chunks, 4 per thread
#pragma unroll
    for (int c = 0; c < 4; ++c) {
        const int idx = tid + c * 256;
        const int r = idx >> 3, ch = idx & 7;
        cpa16(uQ + swzA(r, ch), g_qh + gq0 + (size_t)r * D_MODEL + ch * 8);
    }
    CP_COMMIT();

    auto load_kv = [&](int s, int kb) {
        const uint32_t ub = u0 + AQMAT + s * AKSTG;
#pragma unroll
        for (int c = 0; c < 2; ++c) {
            const int idx = tid * 2 + c;             // 512 chunks = 64 rows x 8
            const int r = idx >> 3, ch = idx & 7;
            const uint32_t sw = swzA(r, ch);
            const size_t ga = ((size_t)b * SEQ + (size_t)kb * 64 + r) * D_MODEL + h * HD + ch * 8;
            cpa16(ub + sw,         g_kh + ga);
            cpa16(ub + AKMAT + sw, g_vh + ga);
        }
        CP_COMMIT();
    };

    load_kv(0, 0);
    asm volatile("cp.async.wait_group 0;" ::: "memory");
    __syncthreads();

    // ---- q fragments (A, m16k16), once
    uint32_t qf[4][4];
    {
        const int arow = wm + (lane & 15);
#pragma unroll
        for (int ks = 0; ks < 4; ++ks)
            LDSM_X4(qf[ks], uQ + swzA(arow, ks * 2 + (lane >> 4)));
    }

    float acc[8][4] = {};
    float m0 = -1e30f, m1 = -1e30f, l0 = 0.f, l1 = 0.f;
    const int nkb = 2 * qt + 2;
    const int qrow0 = qt * 128 + wm;

    for (int kb = 0; kb < nkb; ++kb) {
        const int s = kb & 1;
        if (kb + 1 < nkb) {
            load_kv(s ^ 1, kb + 1);
            asm volatile("cp.async.wait_group 1;" ::: "memory");
        } else {
            asm volatile("cp.async.wait_group 0;" ::: "memory");
        }
        __syncthreads();

        const bool active = (kb * 64 <= qrow0 + 15);
        if (active) {
            const uint32_t uK = u0 + AQMAT + s * AKSTG;
            const uint32_t uV = uK + AKMAT;

            // ---- S = q k^T (plain fp16)
            float sc[8][4] = {};
#pragma unroll
            for (int ks = 0; ks < 4; ++ks) {
                const int bch = ks * 2 + ((lane >> 3) & 1);
                const int brow = (lane & 7) + ((lane >> 4) << 3);
#pragma unroll
                for (int np = 0; np < 4; ++np) {
                    uint32_t k4[4];
                    LDSM_X4(k4, uK + swzA(np * 16 + brow, bch));
                    mma_f16(sc[2 * np],     qf[ks], &k4[0]);
                    mma_f16(sc[2 * np + 1], qf[ks], &k4[2]);
                }
            }

            // ---- scale (base-2 domain) + mask + online softmax
            const float SCL2 = 0.18033688011112042f;   // 0.125 * log2(e)
            const bool domask = (kb * 64 + 63 > qrow0);
            const int r0 = qrow0 + (lane >> 2);
            float mt0 = -1e30f, mt1 = -1e30f;
#pragma unroll
            for (int nt = 0; nt < 8; ++nt) {
#pragma unroll
                for (int j = 0; j < 4; ++j) sc[nt][j] *= SCL2;
                if (domask) {
                    const int colb = kb * 64 + nt * 8 + 2 * (lane & 3);
                    if (colb     > r0)     sc[nt][0] = -1e30f;
                    if (colb + 1 > r0)     sc[nt][1] = -1e30f;
                    if (colb     > r0 + 8) sc[nt][2] = -1e30f;
                    if (colb + 1 > r0 + 8) sc[nt][3] = -1e30f;
                }
                mt0 = fmaxf(mt0, fmaxf(sc[nt][0], sc[nt][1]));
                mt1 = fmaxf(mt1, fmaxf(sc[nt][2], sc[nt][3]));
            }
            mt0 = fmaxf(mt0, __shfl_xor_sync(0xffffffffu, mt0, 1));
            mt0 = fmaxf(mt0, __shfl_xor_sync(0xffffffffu, mt0, 2));
            mt1 = fmaxf(mt1, __shfl_xor_sync(0xffffffffu, mt1, 1));
            mt1 = fmaxf(mt1, __shfl_xor_sync(0xffffffffu, mt1, 2));
            const float mn0 = fmaxf(m0, mt0), mn1 = fmaxf(m1, mt1);
            const float a0 = exp2f(m0 - mn0), a1 = exp2f(m1 - mn1);
            m0 = mn0; m1 = mn1;

            float s0 = 0.f, s1 = 0.f;
            uint32_t ph[4][4];
#pragma unroll
            for (int nt = 0; nt < 8; ++nt) {
                float p0, p1, p2, p3;
                if (nt & 1) {   // poly half: FMA/ALU pipes
                    p0 = fexp2(sc[nt][0] - mn0);
                    p1 = fexp2(sc[nt][1] - mn0);
                    p2 = fexp2(sc[nt][2] - mn1);
                    p3 = fexp2(sc[nt][3] - mn1);
                } else {        // MUFU half
                    p0 = exp2f(sc[nt][0] - mn0);
                    p1 = exp2f(sc[nt][1] - mn0);
                    p2 = exp2f(sc[nt][2] - mn1);
                    p3 = exp2f(sc[nt][3] - mn1);
                }
                s0 += p0 + p1;
                s1 += p2 + p3;
                const int ks = nt >> 1, pos = (nt & 1) * 2;
                ph[ks][pos]     = pack_h2(p0, p1);
                ph[ks][pos + 1] = pack_h2(p2, p3);
            }
            s0 += __shfl_xor_sync(0xffffffffu, s0, 1);
            s0 += __shfl_xor_sync(0xffffffffu, s0, 2);
            s1 += __shfl_xor_sync(0xffffffffu, s1, 1);
            s1 += __shfl_xor_sync(0xffffffffu, s1, 2);
            l0 = l0 * a0 + s0;
            l1 = l1 * a1 + s1;
#pragma unroll
            for (int nt = 0; nt < 8; ++nt) {
                acc[nt][0] *= a0; acc[nt][1] *= a0;
                acc[nt][2] *= a1; acc[nt][3] *= a1;
            }

            // ---- O += P V (plain fp16, V via ldmatrix.trans)
#pragma unroll
            for (int ks = 0; ks < 4; ++ks) {
                const int vrow = ks * 16 + (lane & 7) + (((lane >> 3) & 1) << 3);
#pragma unroll
                for (int np = 0; np < 4; ++np) {
                    uint32_t v4[4];
                    LDSM_X4_T(v4, uV + swzA(vrow, np * 2 + (lane >> 4)));
                    mma_f16(acc[2 * np],     ph[ks], &v4[0]);
                    mma_f16(acc[2 * np + 1], ph[ks], &v4[2]);
                }
            }
        }
        __syncthreads();
    }

    // ---- epilogue: normalize, write plain fp16 O-proj A buffer
    const float i0 = 1.0f / l0, i1 = 1.0f / l1;
    const size_t gr0 = ((size_t)b * SEQ + qrow0 + (lane >> 2)) * D_MODEL + h * HD + 2 * (lane & 3);
#pragma unroll
    for (int nt = 0; nt < 8; ++nt) {
        *(uint32_t*)&g_ah[gr0 + nt * 8] =
            pack_h2(acc[nt][0] * i0, acc[nt][1] * i0);
        *(uint32_t*)&g_ah[gr0 + 8 * D_MODEL + nt * 8] =
            pack_h2(acc[nt][2] * i1, acc[nt][3] * i1);
    }
}

// ---------------------------------------------------------------------------
extern "C" void kernel_launch(void* const* d_in, const int* in_sizes, int n_in,
                              void* d_out, int out_size) {
    const float* x  = (const float*)d_in[0];
    const float* Wq = (const float*)d_in[1];
    const float* Wk = (const float*)d_in[2];
    const float* Wv = (const float*)d_in[3];
    const float* Wo = (const float*)d_in[4];
    const float* qw = (const float*)d_in[5];
    const float* kw = (const float*)d_in[6];
    float* out = (float*)d_out;

    __half *x16, *q16, *k16, *vh, *ah, *wth, *wtl;
    cudaGetSymbolAddress((void**)&x16, g_x16);
    cudaGetSymbolAddress((void**)&q16, g_q16);
    cudaGetSymbolAddress((void**)&k16, g_k16);
    cudaGetSymbolAddress((void**)&vh,  g_vh);
    cudaGetSymbolAddress((void**)&ah,  g_ah);
    cudaGetSymbolAddress((void**)&wth, g_wth);
    cudaGetSymbolAddress((void**)&wtl, g_wtl);

    const int NEL = M_ROWS * D_MODEL;
    const size_t WSZ = (size_t)D_MODEL * D_MODEL;

    cvt_kernel<<<NEL / (256 * 4), 256>>>(x, x16);
    wsplit_kernel<<<dim3(32, 32, 4), 256>>>(Wq, Wk, Wv, Wo);

    cudaFuncSetAttribute(hmma_gemm, cudaFuncAttributeMaxDynamicSharedMemorySize, GEMM_SMEM);
    // fused QKV: N = 3072, fp16 outputs (q/k raw, v final)
    hmma_gemm<<<dim3(3 * D_MODEL / 128, M_ROWS / 128), 256, GEMM_SMEM>>>(
        x16, wth, wtl, nullptr, q16, k16, vh);

    rmsrope_kernel<<<dim3((M_ROWS * N_HEADS) / 8, 2), 256>>>(qw, kw);

    cudaFuncSetAttribute(attn_hmma, cudaFuncAttributeMaxDynamicSharedMemorySize, ATT_SMEM);
    attn_hmma<<<dim3(SEQ / 128, N_HEADS, BATCH), 256, ATT_SMEM>>>();

    // O projection (f32 out)
    hmma_gemm<<<dim3(D_MODEL / 128, M_ROWS / 128), 256, GEMM_SMEM>>>(
        ah, wth + 3 * WSZ, wtl + 3 * WSZ, out, nullptr, nullptr, nullptr);
}

// round 13
// speedup vs baseline: 3.0558x; 1.0931x over previous
#include <cuda_runtime.h>
#include <cuda_fp16.h>
#include <math.h>
#include <cstdint>

#define D_MODEL 1024
#define N_HEADS 16
#define HD      64
#define SEQ     2048
#define BATCH   2
#define M_ROWS  (BATCH * SEQ)   // 4096

// ---------------- scratch (__device__ globals; no allocs allowed) ----------
__device__ __half g_x16[M_ROWS * D_MODEL];         // x plain fp16
__device__ __half g_q16[M_ROWS * D_MODEL];         // raw q (pre-rope) fp16
__device__ __half g_k16[M_ROWS * D_MODEL];         // raw k (pre-rope) fp16
__device__ __half g_qh[M_ROWS * D_MODEL];          // roped q fp16
__device__ __half g_kh[M_ROWS * D_MODEL];          // roped k fp16
__device__ __half g_vh[M_ROWS * D_MODEL];          // v fp16
__device__ __half g_ah[M_ROWS * D_MODEL];          // attention out fp16
__device__ __half g_wth[4 * D_MODEL * D_MODEL];    // W^T split hi, [w][n][k]
__device__ __half g_wtl[4 * D_MODEL * D_MODEL];    // W^T split lo

// ---------------- PTX helpers (portable: sm_80+ features only) -------------
__device__ __forceinline__ uint32_t smem_to_u32(const void* p) {
    uint32_t a;
    asm("{ .reg .u64 t; cvta.to.shared.u64 t, %1; cvt.u32.u64 %0, t; }" : "=r"(a) : "l"(p));
    return a;
}
__device__ __forceinline__ void cpa16(uint32_t d, const void* s) {
    asm volatile("cp.async.cg.shared.global [%0], [%1], 16;" :: "r"(d), "l"(s));
}
#define CP_COMMIT() asm volatile("cp.async.commit_group;" ::: "memory")
#define LDSM_X4(r, a) \
    asm volatile("ldmatrix.sync.aligned.m8n8.x4.shared.b16 {%0,%1,%2,%3}, [%4];" \
                 : "=r"((r)[0]), "=r"((r)[1]), "=r"((r)[2]), "=r"((r)[3]) : "r"(a))
#define LDSM_X4_T(r, a) \
    asm volatile("ldmatrix.sync.aligned.m8n8.x4.trans.shared.b16 {%0,%1,%2,%3}, [%4];" \
                 : "=r"((r)[0]), "=r"((r)[1]), "=r"((r)[2]), "=r"((r)[3]) : "r"(a))
#define LDSM_X2(r, a) \
    asm volatile("ldmatrix.sync.aligned.m8n8.x2.shared.b16 {%0,%1}, [%2];" \
                 : "=r"((r)[0]), "=r"((r)[1]) : "r"(a))
__device__ __forceinline__ void mma_f16(float* c, const uint32_t* a, const uint32_t* b) {
    asm volatile("mma.sync.aligned.m16n8k16.row.col.f32.f16.f16.f32 "
                 "{%0,%1,%2,%3}, {%4,%5,%6,%7}, {%8,%9}, {%0,%1,%2,%3};"
                 : "+f"(c[0]), "+f"(c[1]), "+f"(c[2]), "+f"(c[3])
                 : "r"(a[0]), "r"(a[1]), "r"(a[2]), "r"(a[3]), "r"(b[0]), "r"(b[1]));
}
__device__ __forceinline__ uint32_t pack_h2(float lo, float hi) {
    __half2 t = __halves2half2(__float2half_rn(lo), __float2half_rn(hi));
    return *(uint32_t*)&t;
}

// GEMM tiles: 64B logical rows (4 chunks); 128B line = 2 rows.
__device__ __forceinline__ uint32_t swz(int r, int ch) {
    return (uint32_t)(((r >> 1) << 7) + (((((r & 1) << 2) + ch) ^ ((r >> 1) & 7)) << 4));
}
// Attention tiles: 128B rows (8 chunks), SW128 atom. ch in 0..7.
__device__ __forceinline__ uint32_t swzA(int r, int ch) {
    return (uint32_t)((r << 7) + ((ch ^ (r & 7)) << 4));
}

// 2^y on FMA/ALU pipes, y <= 0 (poly half of the hybrid softmax)
__device__ __forceinline__ float fexp2(float y) {
    y = fmaxf(y, -120.0f);
    const float z = y + 12582912.0f;              // round-to-nearest int
    const int   n = __float_as_int(z) - 0x4B400000;
    const float f = y - (z - 12582912.0f);        // in [-0.5, 0.5]
    float p = 0.0013333558f;
    p = fmaf(p, f, 0.009618129f);
    p = fmaf(p, f, 0.05550411f);
    p = fmaf(p, f, 0.24022651f);
    p = fmaf(p, f, 0.69314718f);
    p = fmaf(p, f, 1.0f);
    return p * __int_as_float((n + 127) << 23);
}

// ---------------------------------------------------------------------------
// cvt: fp32 -> fp16 plain, elementwise (for x)
// ---------------------------------------------------------------------------
__global__ __launch_bounds__(256) void cvt_kernel(const float* __restrict__ src,
                                                  __half* __restrict__ dst) {
    const int i = (blockIdx.x * 256 + threadIdx.x) * 4;
    float4 v = *(const float4*)(src + i);
    __half2* D = (__half2*)(dst + i);
    D[0] = __halves2half2(__float2half_rn(v.x), __float2half_rn(v.y));
    D[1] = __halves2half2(__float2half_rn(v.z), __float2half_rn(v.w));
}

// ---------------------------------------------------------------------------
// weight transpose + fp16 split
// ---------------------------------------------------------------------------
__global__ __launch_bounds__(256) void wsplit_kernel(const float* __restrict__ w0,
                                                     const float* __restrict__ w1,
                                                     const float* __restrict__ w2,
                                                     const float* __restrict__ w3) {
    __shared__ float t[32][33];
    const float* W = (blockIdx.z == 0) ? w0 : (blockIdx.z == 1) ? w1 : (blockIdx.z == 2) ? w2 : w3;
    const int nb = blockIdx.x * 32, kb = blockIdx.y * 32;
    const int tx = threadIdx.x & 31, ty = threadIdx.x >> 5;
#pragma unroll
    for (int i = 0; i < 32; i += 8)
        t[ty + i][tx] = W[(size_t)(kb + ty + i) * D_MODEL + nb + tx];
    __syncthreads();
    const size_t base = (size_t)blockIdx.z * D_MODEL * D_MODEL;
#pragma unroll
    for (int i = 0; i < 32; i += 8) {
        float v = t[tx][ty + i];
        __half h = __float2half_rn(v);
        size_t o = base + (size_t)(nb + ty + i) * D_MODEL + kb + tx;
        g_wth[o] = h;
        g_wtl[o] = __float2half_rn(v - __half2float(h));
    }
}

// ---------------------------------------------------------------------------
// HMMA fp16 GEMM, swizzled smem, 2 CTAs/SM.
// B is split (Bh+Bl); the lo term is used only where accuracy matters:
//   QKV fused (Cf==nullptr): segs 0/1 (Q,K) 1-term, seg 2 (V) 2-term.
//   O-proj (Cf!=nullptr): 2-term.
// ---------------------------------------------------------------------------
#define GMAT 8192                     // bytes per matrix tile (128 rows x 64B)
#define GSTAGE (3 * GMAT)             // A, Bh, Bl
#define GEMM_SMEM (2 * GSTAGE)        // 49152 bytes

__global__ __launch_bounds__(256, 2) void hmma_gemm(const __half* __restrict__ A,
                                                    const __half* __restrict__ Bh,
                                                    const __half* __restrict__ Bl,
                                                    float* __restrict__ Cf,
                                                    __half* __restrict__ H0,
                                                    __half* __restrict__ H1,
                                                    __half* __restrict__ H2) {
    extern __shared__ char smg[];
    const uint32_t u0 = smem_to_u32(smg);

    const int tid = threadIdx.x, warp = tid >> 5, lane = tid & 31;
    const int tm = blockIdx.y * 128;
    const int tnG = blockIdx.x * 128;
    const int tn = tnG & 1023;
    const int seg = tnG >> 10;
    const bool useBl = (seg == 2) || (Cf != nullptr);
    const int wm = (warp >> 2) * 64, wn = (warp & 3) * 32;

    const int c0 = tid * 2, c1 = tid * 2 + 1;
    const int r0c = c0 >> 2, h0c = c0 & 3;
    const int r1c = c1 >> 2, h1c = c1 & 3;

    auto load_stage = [&](int s, int kc) {
        const uint32_t ub = u0 + s * GSTAGE;
        {
            const uint32_t sw = swz(r0c, h0c);
            const size_t ga = (size_t)(tm + r0c) * D_MODEL + kc + h0c * 8;
            const size_t gb = (size_t)(tnG + r0c) * D_MODEL + kc + h0c * 8;
            cpa16(ub + sw,        A + ga);
            cpa16(ub + GMAT + sw, Bh + gb);
            if (useBl) cpa16(ub + 2 * GMAT + sw, Bl + gb);
        }
        {
            const uint32_t sw = swz(r1c, h1c);
            const size_t ga = (size_t)(tm + r1c) * D_MODEL + kc + h1c * 8;
            const size_t gb = (size_t)(tnG + r1c) * D_MODEL + kc + h1c * 8;
            cpa16(ub + sw,        A + ga);
            cpa16(ub + GMAT + sw, Bh + gb);
            if (useBl) cpa16(ub + 2 * GMAT + sw, Bl + gb);
        }
        CP_COMMIT();
    };

    float acc[4][4][4] = {};

    load_stage(0, 0);
    const int NKB = D_MODEL / 32;
    for (int kb = 0; kb < NKB; ++kb) {
        const int s = kb & 1;
        if (kb + 1 < NKB) {
            load_stage(s ^ 1, (kb + 1) * 32);
            asm volatile("cp.async.wait_group 1;" ::: "memory");
        } else {
            asm volatile("cp.async.wait_group 0;" ::: "memory");
        }
        __syncthreads();
        const uint32_t uA  = u0 + s * GSTAGE;
        const uint32_t uBh = uA + GMAT;
        const uint32_t uBl = uA + 2 * GMAT;

#pragma unroll
        for (int kk = 0; kk < 2; ++kk) {
            uint32_t bh[4][2], bl[4][2];
            const int brow = wn + (lane & 7);
            const int bch = kk * 2 + ((lane >> 3) & 1);
#pragma unroll
            for (int nt = 0; nt < 4; ++nt) {
                const uint32_t off = swz(brow + nt * 8, bch);
                LDSM_X2(bh[nt], uBh + off);
                if (useBl) LDSM_X2(bl[nt], uBl + off);
            }
            const int arow = wm + (lane & 15);
            const int ach = kk * 2 + (lane >> 4);
#pragma unroll
            for (int mt = 0; mt < 4; ++mt) {
                const uint32_t off = swz(arow + mt * 16, ach);
                uint32_t a4[4];
                LDSM_X4(a4, uA + off);
#pragma unroll
                for (int nt = 0; nt < 4; ++nt) {
                    mma_f16(acc[mt][nt], a4, bh[nt]);
                    if (useBl) mma_f16(acc[mt][nt], a4, bl[nt]);
                }
            }
        }
        __syncthreads();
    }

    __half* H = (seg == 0) ? H0 : (seg == 1) ? H1 : H2;
    if (H != nullptr) {
#pragma unroll
        for (int mt = 0; mt < 4; ++mt) {
#pragma unroll
            for (int nt = 0; nt < 4; ++nt) {
                const int r0 = tm + wm + mt * 16 + (lane >> 2);
                const int cc = tn + wn + nt * 8 + 2 * (lane & 3);
                *(uint32_t*)&H[(size_t)r0 * D_MODEL + cc] =
                    pack_h2(acc[mt][nt][0], acc[mt][nt][1]);
                *(uint32_t*)&H[(size_t)(r0 + 8) * D_MODEL + cc] =
                    pack_h2(acc[mt][nt][2], acc[mt][nt][3]);
            }
        }
    } else {
#pragma unroll
        for (int mt = 0; mt < 4; ++mt) {
#pragma unroll
            for (int nt = 0; nt < 4; ++nt) {
                const int r0 = tm + wm + mt * 16 + (lane >> 2);
                const int cc = tn + wn + nt * 8 + 2 * (lane & 3);
                *(float2*)&Cf[(size_t)r0 * D_MODEL + cc] = make_float2(acc[mt][nt][0], acc[mt][nt][1]);
                *(float2*)&Cf[(size_t)(r0 + 8) * D_MODEL + cc] = make_float2(acc[mt][nt][2], acc[mt][nt][3]);
            }
        }
    }
}

// ---------------------------------------------------------------------------
// Fused per-head RMSNorm + RoPE, fp16 in -> fp16 out
// ---------------------------------------------------------------------------
__global__ __launch_bounds__(256) void rmsrope_kernel(const float* __restrict__ w_q,
                                                      const float* __restrict__ w_k) {
    const int gw   = (blockIdx.x * blockDim.x + threadIdx.x) >> 5;
    const int lane = threadIdx.x & 31;
    const bool isq = (blockIdx.y == 0);
    const __half* src = isq ? g_q16 : g_k16;
    const float*  w   = isq ? w_q : w_k;
    __half* dst = isq ? g_qh : g_kh;
    const int t = (gw / N_HEADS) % SEQ;
    const size_t base = (size_t)gw * HD;

    float x1 = __half2float(src[base + lane]);
    float x2 = __half2float(src[base + lane + 32]);
    float ss = x1 * x1 + x2 * x2;
#pragma unroll
    for (int o = 16; o; o >>= 1) ss += __shfl_xor_sync(0xffffffffu, ss, o);
    const float r = rsqrtf(ss * (1.0f / 64.0f) + 1e-6f);
    x1 *= r * w[lane];
    x2 *= r * w[lane + 32];
    const float inv = exp2f(-(float)lane * 0.41524101186091903f);
    const float ang = (float)t * inv;
    float sn, cs;
    sincosf(ang, &sn, &cs);
    dst[base + lane]      = __float2half_rn(x1 * cs - x2 * sn);
    dst[base + lane + 32] = __float2half_rn(x2 * cs + x1 * sn);
}

// ---------------------------------------------------------------------------
// HMMA flash attention: Q, K, V plain fp16, K-block 128 (halves per-block
// softmax/rescale/barrier overhead), hybrid MUFU+poly softmax.
// ---------------------------------------------------------------------------
#define AQMAT 16384                   // q tile: 128 rows x 128B
#define AKMAT 16384                   // kv tile: 128 rows x 128B
#define AKSTG (2 * AKMAT)             // K, V per stage
#define ATT_SMEM (AQMAT + 2 * AKSTG)  // 81920 bytes

__global__ __launch_bounds__(256) void attn_hmma() {
    extern __shared__ char smA[];
    const uint32_t u0 = smem_to_u32(smA);
    const uint32_t uQ = u0;

    const int tid = threadIdx.x, warp = tid >> 5, lane = tid & 31;
    const int qt = (int)(gridDim.x - 1) - (int)blockIdx.x;   // long CTAs first
    const int h = blockIdx.y, b = blockIdx.z;
    const int wm = warp * 16;
    const size_t gq0 = ((size_t)b * SEQ + (size_t)qt * 128) * D_MODEL + h * HD;

    // ---- load q tile: 128 rows x 8 chunks = 1024 chunks, 4 per thread
#pragma unroll
    for (int c = 0; c < 4; ++c) {
        const int idx = tid + c * 256;
        const int r = idx >> 3, ch = idx & 7;
        cpa16(uQ + swzA(r, ch), g_qh + gq0 + (size_t)r * D_MODEL + ch * 8);
    }
    CP_COMMIT();

    auto load_kv = [&](int s, int kb) {
        const uint32_t ub = u0 + AQMAT + s * AKSTG;
#pragma unroll
        for (int c = 0; c < 4; ++c) {
            const int idx = tid + c * 256;           // 1024 chunks = 128 rows x 8
            const int r = idx >> 3, ch = idx & 7;
            const uint32_t sw = swzA(r, ch);
            const size_t ga = ((size_t)b * SEQ + (size_t)kb * 128 + r) * D_MODEL + h * HD + ch * 8;
            cpa16(ub + sw,         g_kh + ga);
            cpa16(ub + AKMAT + sw, g_vh + ga);
        }
        CP_COMMIT();
    };

    load_kv(0, 0);
    asm volatile("cp.async.wait_group 0;" ::: "memory");
    __syncthreads();

    // ---- q fragments (A, m16k16), once
    uint32_t qf[4][4];
    {
        const int arow = wm + (lane & 15);
#pragma unroll
        for (int ks = 0; ks < 4; ++ks)
            LDSM_X4(qf[ks], uQ + swzA(arow, ks * 2 + (lane >> 4)));
    }

    float acc[8][4] = {};
    float m0 = -1e30f, m1 = -1e30f, l0 = 0.f, l1 = 0.f;
    const int nkb = qt + 1;
    const int qrow0 = qt * 128 + wm;

    for (int kb = 0; kb < nkb; ++kb) {
        const int s = kb & 1;
        if (kb + 1 < nkb) {
            load_kv(s ^ 1, kb + 1);
            asm volatile("cp.async.wait_group 1;" ::: "memory");
        } else {
            asm volatile("cp.async.wait_group 0;" ::: "memory");
        }
        __syncthreads();

        const uint32_t uK = u0 + AQMAT + s * AKSTG;
        const uint32_t uV = uK + AKMAT;

        // ---- S = q k^T over 128 key-cols (16 col-groups)
        float sc[16][4] = {};
#pragma unroll
        for (int ks = 0; ks < 4; ++ks) {
            const int bch = ks * 2 + ((lane >> 3) & 1);
            const int brow = (lane & 7) + ((lane >> 4) << 3);
#pragma unroll
            for (int np = 0; np < 8; ++np) {
                uint32_t k4[4];
                LDSM_X4(k4, uK + swzA(np * 16 + brow, bch));
                mma_f16(sc[2 * np],     qf[ks], &k4[0]);
                mma_f16(sc[2 * np + 1], qf[ks], &k4[2]);
            }
        }

        // ---- scale (base-2 domain) + mask + online softmax
        const float SCL2 = 0.18033688011112042f;   // 0.125 * log2(e)
        const bool domask = (kb == nkb - 1);
        const int r0 = qrow0 + (lane >> 2);
        float mt0 = -1e30f, mt1 = -1e30f;
#pragma unroll
        for (int nt = 0; nt < 16; ++nt) {
#pragma unroll
            for (int j = 0; j < 4; ++j) sc[nt][j] *= SCL2;
            if (domask) {
                const int colb = kb * 128 + nt * 8 + 2 * (lane & 3);
                if (colb     > r0)     sc[nt][0] = -1e30f;
                if (colb + 1 > r0)     sc[nt][1] = -1e30f;
                if (colb     > r0 + 8) sc[nt][2] = -1e30f;
                if (colb + 1 > r0 + 8) sc[nt][3] = -1e30f;
            }
            mt0 = fmaxf(mt0, fmaxf(sc[nt][0], sc[nt][1]));
            mt1 = fmaxf(mt1, fmaxf(sc[nt][2], sc[nt][3]));
        }
        mt0 = fmaxf(mt0, __shfl_xor_sync(0xffffffffu, mt0, 1));
        mt0 = fmaxf(mt0, __shfl_xor_sync(0xffffffffu, mt0, 2));
        mt1 = fmaxf(mt1, __shfl_xor_sync(0xffffffffu, mt1, 1));
        mt1 = fmaxf(mt1, __shfl_xor_sync(0xffffffffu, mt1, 2));
        const float mn0 = fmaxf(m0, mt0), mn1 = fmaxf(m1, mt1);
        const float a0 = exp2f(m0 - mn0), a1 = exp2f(m1 - mn1);
        m0 = mn0; m1 = mn1;

        float s0 = 0.f, s1 = 0.f;
        uint32_t ph[8][4];
#pragma unroll
        for (int nt = 0; nt < 16; ++nt) {
            float p0, p1, p2, p3;
            if (nt & 1) {   // poly half: FMA/ALU pipes
                p0 = fexp2(sc[nt][0] - mn0);
                p1 = fexp2(sc[nt][1] - mn0);
                p2 = fexp2(sc[nt][2] - mn1);
                p3 = fexp2(sc[nt][3] - mn1);
            } else {        // MUFU half
                p0 = exp2f(sc[nt][0] - mn0);
                p1 = exp2f(sc[nt][1] - mn0);
                p2 = exp2f(sc[nt][2] - mn1);
                p3 = exp2f(sc[nt][3] - mn1);
            }
            s0 += p0 + p1;
            s1 += p2 + p3;
            const int ks = nt >> 1, pos = (nt & 1) * 2;
            ph[ks][pos]     = pack_h2(p0, p1);
            ph[ks][pos + 1] = pack_h2(p2, p3);
        }
        s0 += __shfl_xor_sync(0xffffffffu, s0, 1);
        s0 += __shfl_xor_sync(0xffffffffu, s0, 2);
        s1 += __shfl_xor_sync(0xffffffffu, s1, 1);
        s1 += __shfl_xor_sync(0xffffffffu, s1, 2);
        l0 = l0 * a0 + s0;
        l1 = l1 * a1 + s1;
#pragma unroll
        for (int nt = 0; nt < 8; ++nt) {
            acc[nt][0] *= a0; acc[nt][1] *= a0;
            acc[nt][2] *= a1; acc[nt][3] *= a1;
        }

        // ---- O += P V (8 k16 groups, V via ldmatrix.trans)
#pragma unroll
        for (int ks = 0; ks < 8; ++ks) {
            const int vrow = ks * 16 + (lane & 7) + (((lane >> 3) & 1) << 3);
#pragma unroll
            for (int np = 0; np < 4; ++np) {
                uint32_t v4[4];
                LDSM_X4_T(v4, uV + swzA(vrow, np * 2 + (lane >> 4)));
                mma_f16(acc[2 * np],     ph[ks], &v4[0]);
                mma_f16(acc[2 * np + 1], ph[ks], &v4[2]);
            }
        }
        __syncthreads();
    }

    // ---- epilogue: normalize, write plain fp16 O-proj A buffer
    const float i0 = 1.0f / l0, i1 = 1.0f / l1;
    const size_t gr0 = ((size_t)b * SEQ + qrow0 + (lane >> 2)) * D_MODEL + h * HD + 2 * (lane & 3);
#pragma unroll
    for (int nt = 0; nt < 8; ++nt) {
        *(uint32_t*)&g_ah[gr0 + nt * 8] =
            pack_h2(acc[nt][0] * i0, acc[nt][1] * i0);
        *(uint32_t*)&g_ah[gr0 + 8 * D_MODEL + nt * 8] =
            pack_h2(acc[nt][2] * i1, acc[nt][3] * i1);
    }
}

// ---------------------------------------------------------------------------
extern "C" void kernel_launch(void* const* d_in, const int* in_sizes, int n_in,
                              void* d_out, int out_size) {
    const float* x  = (const float*)d_in[0];
    const float* Wq = (const float*)d_in[1];
    const float* Wk = (const float*)d_in[2];
    const float* Wv = (const float*)d_in[3];
    const float* Wo = (const float*)d_in[4];
    const float* qw = (const float*)d_in[5];
    const float* kw = (const float*)d_in[6];
    float* out = (float*)d_out;

    __half *x16, *q16, *k16, *vh, *ah, *wth, *wtl;
    cudaGetSymbolAddress((void**)&x16, g_x16);
    cudaGetSymbolAddress((void**)&q16, g_q16);
    cudaGetSymbolAddress((void**)&k16, g_k16);
    cudaGetSymbolAddress((void**)&vh,  g_vh);
    cudaGetSymbolAddress((void**)&ah,  g_ah);
    cudaGetSymbolAddress((void**)&wth, g_wth);
    cudaGetSymbolAddress((void**)&wtl, g_wtl);

    const int NEL = M_ROWS * D_MODEL;
    const size_t WSZ = (size_t)D_MODEL * D_MODEL;

    cvt_kernel<<<NEL / (256 * 4), 256>>>(x, x16);
    wsplit_kernel<<<dim3(32, 32, 4), 256>>>(Wq, Wk, Wv, Wo);

    cudaFuncSetAttribute(hmma_gemm, cudaFuncAttributeMaxDynamicSharedMemorySize, GEMM_SMEM);
    // fused QKV: N = 3072, fp16 outputs (q/k raw 1-term, v 2-term)
    hmma_gemm<<<dim3(3 * D_MODEL / 128, M_ROWS / 128), 256, GEMM_SMEM>>>(
        x16, wth, wtl, nullptr, q16, k16, vh);

    rmsrope_kernel<<<dim3((M_ROWS * N_HEADS) / 8, 2), 256>>>(qw, kw);

    cudaFuncSetAttribute(attn_hmma, cudaFuncAttributeMaxDynamicSharedMemorySize, ATT_SMEM);
    attn_hmma<<<dim3(SEQ / 128, N_HEADS, BATCH), 256, ATT_SMEM>>>();

    // O projection (f32 out, 2-term)
    hmma_gemm<<<dim3(D_MODEL / 128, M_ROWS / 128), 256, GEMM_SMEM>>>(
        ah, wth + 3 * WSZ, wtl + 3 * WSZ, out, nullptr, nullptr, nullptr);
}